// round 2
// baseline (speedup 1.0000x reference)
#include <cuda_runtime.h>
#include <cstdint>

#define DINLINE __device__ __forceinline__

static __device__ constexpr float S3 = 0.57735026918962576451f;  // 1/sqrt(3)

// ======================= low-level helpers =======================
DINLINE uint32_t smem_u32(const void* p) {
    uint32_t a;
    asm("{ .reg .u64 t; cvta.to.shared.u64 t, %1; cvt.u32.u64 %0, t; }" : "=r"(a) : "l"(p));
    return a;
}
DINLINE uint32_t cvt_tf32(float f) {
    uint32_t u;
    asm("cvt.rna.tf32.f32 %0, %1;" : "=r"(u) : "f"(f));
    return u;
}
DINLINE uint32_t lds_tf32(uint32_t a) {
    float v;
    asm volatile("ld.shared.f32 %0, [%1];" : "=f"(v) : "r"(a));
    return cvt_tf32(v);
}
DINLINE uint4 lds128(uint32_t a) {
    uint4 v;
    asm volatile("ld.shared.v4.b32 {%0,%1,%2,%3}, [%4];"
                 : "=r"(v.x), "=r"(v.y), "=r"(v.z), "=r"(v.w) : "r"(a));
    return v;
}
DINLINE void sts_f32(uint32_t a, float v) {
    asm volatile("st.shared.f32 [%0], %1;" :: "r"(a), "f"(v));
}
DINLINE void sts_zero16(uint32_t a) {
    asm volatile("st.shared.v4.b32 [%0], {%1,%1,%1,%1};" :: "r"(a), "r"(0u));
}
DINLINE void cpa16(uint32_t d, const float* s) {
    asm volatile("cp.async.cg.shared.global [%0], [%1], 16;" :: "r"(d), "l"(s));
}
#define CP_COMMIT() asm volatile("cp.async.commit_group;")
#define CP_WAIT(N)  asm volatile("cp.async.wait_group " #N ";")

DINLINE void mma8(float (&d)[4], uint32_t a0, uint32_t a1, uint32_t a2, uint32_t a3,
                  uint32_t b0, uint32_t b1) {
    asm volatile(
        "mma.sync.aligned.m16n8k8.row.col.f32.tf32.tf32.f32 "
        "{%0,%1,%2,%3}, {%4,%5,%6,%7}, {%8,%9}, {%0,%1,%2,%3};"
        : "+f"(d[0]), "+f"(d[1]), "+f"(d[2]), "+f"(d[3])
        : "r"(a0), "r"(a1), "r"(a2), "r"(a3), "r"(b0), "r"(b1));
}

// ======================= geometry =======================
// CTA: 256 threads = 8 warps; tile = 64 rows x 512 out cols.
// warp_m = wid&3 (rows 16*wm..), warp_n = wid>>2 (w-cols 64*wn..)
// 8 schedule steps, each one GEMM (64x128 out, K=128) via mma.sync m16n8k8 tf32.
static constexpr int XPITCHF = 132;                 // floats per X smem row (pad for banks)
static constexpr uint32_t XPITCHB = XPITCHF * 4;    // 528 bytes
static constexpr uint32_t W_BYTES = 65536;          // one frag-ordered weight matrix
static constexpr uint32_t X_BYTES = 64 * XPITCHB;   // 33792
static constexpr uint32_t OFF_WA = 0;
static constexpr uint32_t OFF_WB = W_BYTES;
static constexpr uint32_t OFF_X0 = 2 * W_BYTES;             // XB0
static constexpr uint32_t OFF_X1 = 2 * W_BYTES + X_BYTES;   // XB1
static constexpr uint32_t SMEM_TOTAL = 2 * W_BYTES + 2 * X_BYTES;  // 198656

// Fragment-ordered weights: g_Wf[j][half][kc][lane][sub*2+pair]
// value = Wt[w][k], w = half*64 + sub*8 + lane/4, k = kc*8 + lane%4 + pair*4
// j: 0=W000, 1=W011, 2=W110, 3=W101 (transposed from [k][w] source, tf32-rounded)
__device__ __align__(16) float g_Wf[4 * 16384];

__global__ void o3tp_prep(const float* __restrict__ W000, const float* __restrict__ W011,
                          const float* __restrict__ W110, const float* __restrict__ W101) {
    int f = blockIdx.x * blockDim.x + threadIdx.x;   // 0 .. 65535
    int j = f >> 14;
    int r = f & 16383;
    int half = r >> 13;
    int r2 = r & 8191;
    int kc = r2 >> 9;
    int r3 = r2 & 511;
    int lane = r3 >> 4;
    int idx = r3 & 15;
    int sub = idx >> 1;
    int pair = idx & 1;
    int w = half * 64 + sub * 8 + (lane >> 2);
    int k = kc * 8 + (lane & 3) + pair * 4;
    const float* src = (j == 0) ? W000 : (j == 1) ? W011 : (j == 2) ? W110 : W101;
    g_Wf[f] = __uint_as_float(cvt_tf32(src[k * 128 + w]));
}

// ======================= fills =======================
DINLINE void fill_w(uint32_t dst, int j, int t) {
    const float* src = g_Wf + j * 16384;
    #pragma unroll
    for (int e = 0; e < 16; ++e) {
        int ch = e * 256 + t;
        cpa16(dst + (uint32_t)ch * 16u, src + ch * 4);
    }
}
// X0: rows of 128 floats (x[:, 0:128]) -> [r][k], pitch 132
DINLINE void fill_x0(uint32_t dst, const float* __restrict__ x, long row0, int n, int t) {
    #pragma unroll
    for (int e = 0; e < 8; ++e) {
        int ch = e * 256 + t;
        int r = ch >> 5;
        int c = ch & 31;
        uint32_t d = dst + (uint32_t)r * XPITCHB + (uint32_t)c * 16u;
        long gr = row0 + r;
        if (gr < (long)n) cpa16(d, x + gr * 512 + c * 4);
        else              sts_zero16(d);
    }
}
// X1_i: de-interleave x[:, 128 + 3u + i] -> [r][u], pitch 132
DINLINE void fill_x1(uint32_t dst, const float* __restrict__ x, long row0, int n, int i, int t) {
    #pragma unroll
    for (int e = 0; e < 32; ++e) {
        int flat = e * 256 + t;
        int r = flat >> 7;
        int u = flat & 127;
        long gr = row0 + r;
        float v = (gr < (long)n) ? __ldg(x + gr * 512 + 128 + 3 * u + i) : 0.0f;
        sts_f32(dst + (uint32_t)r * XPITCHB + (uint32_t)u * 4u, v);
    }
}

// ======================= GEMM step (K=128) =======================
DINLINE void gemm_k128(uint32_t xbase, uint32_t wbase, float (&cur)[8][4],
                       int wm, int wn, int lane) {
    const uint32_t xa = xbase + ((uint32_t)(16 * wm + (lane >> 2)) * XPITCHB
                                 + (uint32_t)(lane & 3) * 4u);
    const uint32_t wb = wbase + (uint32_t)wn * 32768u + (uint32_t)lane * 64u;
    #pragma unroll
    for (int kc = 0; kc < 16; ++kc) {
        uint32_t a0 = lds_tf32(xa + kc * 32);
        uint32_t a2 = lds_tf32(xa + kc * 32 + 16);
        uint32_t a1 = lds_tf32(xa + kc * 32 + 8 * XPITCHB);
        uint32_t a3 = lds_tf32(xa + kc * 32 + 8 * XPITCHB + 16);
        uint4 b01 = lds128(wb + kc * 2048);
        uint4 b23 = lds128(wb + kc * 2048 + 16);
        uint4 b45 = lds128(wb + kc * 2048 + 32);
        uint4 b67 = lds128(wb + kc * 2048 + 48);
        mma8(cur[0], a0, a1, a2, a3, b01.x, b01.y);
        mma8(cur[1], a0, a1, a2, a3, b01.z, b01.w);
        mma8(cur[2], a0, a1, a2, a3, b23.x, b23.y);
        mma8(cur[3], a0, a1, a2, a3, b23.z, b23.w);
        mma8(cur[4], a0, a1, a2, a3, b45.x, b45.y);
        mma8(cur[5], a0, a1, a2, a3, b45.z, b45.w);
        mma8(cur[6], a0, a1, a2, a3, b67.x, b67.y);
        mma8(cur[7], a0, a1, a2, a3, b67.z, b67.w);
    }
}

DINLINE void zero8x4(float (&a)[8][4]) {
    #pragma unroll
    for (int s = 0; s < 8; ++s)
        #pragma unroll
        for (int q = 0; q < 4; ++q) a[s][q] = 0.0f;
}

// ======================= main kernel =======================
__global__ void __launch_bounds__(256, 1) o3tp_main(
    const float* __restrict__ x,     // (n, 512)
    const float* __restrict__ y,     // (n, 4)
    const float* __restrict__ bias,  // (128,)
    float* __restrict__ out,         // (n, 512)
    int n)
{
    extern __shared__ char smem[];
    const uint32_t sb = smem_u32(smem);
    const int t = threadIdx.x;
    const int wid = t >> 5;
    const int lane = t & 31;
    const int wm = wid & 3;
    const int wn = wid >> 2;
    const long row0 = (long)blockIdx.x * 64;

    // rows this thread's c-frags map to
    const long gra = row0 + 16 * wm + (lane >> 2);
    const long grb = gra + 8;
    const bool va = gra < (long)n;
    const bool vb = grb < (long)n;
    float ya[4] = {0, 0, 0, 0}, yb[4] = {0, 0, 0, 0};
    if (va) { float4 v = *(const float4*)(y + gra * 4); ya[0] = v.x; ya[1] = v.y; ya[2] = v.z; ya[3] = v.w; }
    if (vb) { float4 v = *(const float4*)(y + grb * 4); yb[0] = v.x; yb[1] = v.y; yb[2] = v.z; yb[3] = v.w; }

    float o0a[8][4], p011[8][4], cur[8][4];
    zero8x4(o0a);

    // ---- prologue fills ----
    fill_x0(sb + OFF_X0, x, row0, n, t);
    fill_w(sb + OFF_WA, 0, t);           // W000
    CP_COMMIT();                          // g1
    fill_w(sb + OFF_WB, 1, t);           // W011
    CP_COMMIT();                          // g2
    fill_x1(sb + OFF_X1, x, row0, n, 0, t);  // X1_0 (inline LDG+STS)
    CP_WAIT(1);                           // g1 done
    __syncthreads();

    // ---- s0: P000 = X0 @ W000 -> fold o0 += y0 * P000 ----
    zero8x4(cur);
    gemm_k128(sb + OFF_X0, sb + OFF_WA, cur, wm, wn, lane);
    #pragma unroll
    for (int s = 0; s < 8; ++s) {
        o0a[s][0] += ya[0] * cur[s][0]; o0a[s][1] += ya[0] * cur[s][1];
        o0a[s][2] += yb[0] * cur[s][2]; o0a[s][3] += yb[0] * cur[s][3];
    }
    __syncthreads();
    fill_w(sb + OFF_WA, 2, t);           // W110
    CP_COMMIT();                          // g3
    CP_WAIT(1);                           // g2 (W011) done
    __syncthreads();

    // ---- s1: P011 = X0 @ W011 (retained) ----
    zero8x4(p011);
    gemm_k128(sb + OFF_X0, sb + OFF_WB, p011, wm, wn, lane);
    __syncthreads();
    fill_w(sb + OFF_WB, 3, t);           // W101
    CP_COMMIT();                          // g4
    fill_x1(sb + OFF_X0, x, row0, n, 1, t);  // X1_1 over dead X0
    CP_WAIT(1);                           // g3 (W110) done
    __syncthreads();

    // ---- s2: Q0 = X1_0 @ W110 -> fold o0 += s*y1_0*Q0 ----
    zero8x4(cur);
    gemm_k128(sb + OFF_X1, sb + OFF_WA, cur, wm, wn, lane);
    {
        float fa = S3 * ya[1], fb = S3 * yb[1];
        #pragma unroll
        for (int s = 0; s < 8; ++s) {
            o0a[s][0] += fa * cur[s][0]; o0a[s][1] += fa * cur[s][1];
            o0a[s][2] += fb * cur[s][2]; o0a[s][3] += fb * cur[s][3];
        }
    }
    CP_WAIT(0);                           // g4 (W101) done
    __syncthreads();

    // ---- s3: R0 = X1_0 @ W101 -> store o1_0 ----
    zero8x4(cur);
    gemm_k128(sb + OFF_X1, sb + OFF_WB, cur, wm, wn, lane);
    #pragma unroll
    for (int s = 0; s < 8; ++s) {
        int wcol = 64 * wn + 8 * s + 2 * (lane & 3);
        int c0 = 128 + 3 * wcol + 0;
        if (va) {
            out[gra * 512 + c0]     = S3 * (ya[1] * p011[s][0] + ya[0] * cur[s][0]);
            out[gra * 512 + c0 + 3] = S3 * (ya[1] * p011[s][1] + ya[0] * cur[s][1]);
        }
        if (vb) {
            out[grb * 512 + c0]     = S3 * (yb[1] * p011[s][2] + yb[0] * cur[s][2]);
            out[grb * 512 + c0 + 3] = S3 * (yb[1] * p011[s][3] + yb[0] * cur[s][3]);
        }
    }
    __syncthreads();
    fill_x1(sb + OFF_X1, x, row0, n, 2, t);  // X1_2 over dead X1_0
    __syncthreads();

    // ---- s4: Q1 = X1_1 @ W110 -> fold ----
    zero8x4(cur);
    gemm_k128(sb + OFF_X0, sb + OFF_WA, cur, wm, wn, lane);
    {
        float fa = S3 * ya[2], fb = S3 * yb[2];
        #pragma unroll
        for (int s = 0; s < 8; ++s) {
            o0a[s][0] += fa * cur[s][0]; o0a[s][1] += fa * cur[s][1];
            o0a[s][2] += fb * cur[s][2]; o0a[s][3] += fb * cur[s][3];
        }
    }

    // ---- s5: R1 = X1_1 @ W101 -> store o1_1 ----
    zero8x4(cur);
    gemm_k128(sb + OFF_X0, sb + OFF_WB, cur, wm, wn, lane);
    #pragma unroll
    for (int s = 0; s < 8; ++s) {
        int wcol = 64 * wn + 8 * s + 2 * (lane & 3);
        int c0 = 128 + 3 * wcol + 1;
        if (va) {
            out[gra * 512 + c0]     = S3 * (ya[2] * p011[s][0] + ya[0] * cur[s][0]);
            out[gra * 512 + c0 + 3] = S3 * (ya[2] * p011[s][1] + ya[0] * cur[s][1]);
        }
        if (vb) {
            out[grb * 512 + c0]     = S3 * (yb[2] * p011[s][2] + yb[0] * cur[s][2]);
            out[grb * 512 + c0 + 3] = S3 * (yb[2] * p011[s][3] + yb[0] * cur[s][3]);
        }
    }

    // ---- s6: Q2 = X1_2 @ W110 -> fold, store o0 ----
    zero8x4(cur);
    gemm_k128(sb + OFF_X1, sb + OFF_WA, cur, wm, wn, lane);
    {
        float fa = S3 * ya[3], fb = S3 * yb[3];
        #pragma unroll
        for (int s = 0; s < 8; ++s) {
            o0a[s][0] += fa * cur[s][0]; o0a[s][1] += fa * cur[s][1];
            o0a[s][2] += fb * cur[s][2]; o0a[s][3] += fb * cur[s][3];
        }
    }
    #pragma unroll
    for (int s = 0; s < 8; ++s) {
        int wcol = 64 * wn + 8 * s + 2 * (lane & 3);
        float b0 = __ldg(bias + wcol), b1 = __ldg(bias + wcol + 1);
        if (va) {
            float2 v = make_float2(o0a[s][0] + b0, o0a[s][1] + b1);
            *(float2*)(out + gra * 512 + wcol) = v;
        }
        if (vb) {
            float2 v = make_float2(o0a[s][2] + b0, o0a[s][3] + b1);
            *(float2*)(out + grb * 512 + wcol) = v;
        }
    }

    // ---- s7: R2 = X1_2 @ W101 -> store o1_2 ----
    zero8x4(cur);
    gemm_k128(sb + OFF_X1, sb + OFF_WB, cur, wm, wn, lane);
    #pragma unroll
    for (int s = 0; s < 8; ++s) {
        int wcol = 64 * wn + 8 * s + 2 * (lane & 3);
        int c0 = 128 + 3 * wcol + 2;
        if (va) {
            out[gra * 512 + c0]     = S3 * (ya[3] * p011[s][0] + ya[0] * cur[s][0]);
            out[gra * 512 + c0 + 3] = S3 * (ya[3] * p011[s][1] + ya[0] * cur[s][1]);
        }
        if (vb) {
            out[grb * 512 + c0]     = S3 * (yb[3] * p011[s][2] + yb[0] * cur[s][2]);
            out[grb * 512 + c0 + 3] = S3 * (yb[3] * p011[s][3] + yb[0] * cur[s][3]);
        }
    }
}

// ======================= launch =======================
extern "C" void kernel_launch(void* const* d_in, const int* in_sizes, int n_in,
                              void* d_out, int out_size) {
    const float* x    = (const float*)d_in[0];
    const float* y    = (const float*)d_in[1];
    const float* W000 = (const float*)d_in[2];
    const float* W011 = (const float*)d_in[3];
    const float* W101 = (const float*)d_in[4];
    const float* W110 = (const float*)d_in[5];
    const float* bias = (const float*)d_in[6];

    int n = in_sizes[1] / 4;  // y is (n, 4)
    if (n <= 0) return;

    // prep: j order = W000, W011, W110, W101
    o3tp_prep<<<256, 256>>>(W000, W011, W110, W101);

    cudaFuncSetAttribute(o3tp_main, cudaFuncAttributeMaxDynamicSharedMemorySize, SMEM_TOTAL);
    int grid = (n + 63) / 64;
    o3tp_main<<<grid, 256, SMEM_TOTAL>>>(x, y, bias, (float*)d_out, n);
}

// round 3
// speedup vs baseline: 1.3795x; 1.3795x over previous
#include <cuda_runtime.h>
#include <cstdint>

#define DINLINE __device__ __forceinline__

static __device__ constexpr float S3 = 0.57735026918962576451f;  // 1/sqrt(3)

// ======================= low-level helpers =======================
DINLINE uint32_t smem_u32(const void* p) {
    uint32_t a;
    asm("{ .reg .u64 t; cvta.to.shared.u64 t, %1; cvt.u32.u64 %0, t; }" : "=r"(a) : "l"(p));
    return a;
}
DINLINE uint32_t cvt_tf32(float f) {
    uint32_t u;
    asm("cvt.rna.tf32.f32 %0, %1;" : "=r"(u) : "f"(f));
    return u;
}
DINLINE uint4 lds128(uint32_t a) {
    uint4 v;
    asm volatile("ld.shared.v4.b32 {%0,%1,%2,%3}, [%4];"
                 : "=r"(v.x), "=r"(v.y), "=r"(v.z), "=r"(v.w) : "r"(a));
    return v;
}
DINLINE float lds_f32(uint32_t a) {
    float v;
    asm volatile("ld.shared.f32 %0, [%1];" : "=f"(v) : "r"(a));
    return v;
}
DINLINE void sts_b32(uint32_t a, uint32_t v) {
    asm volatile("st.shared.b32 [%0], %1;" :: "r"(a), "r"(v));
}
DINLINE void sts_f32x2(uint32_t a, float v0, float v1) {
    asm volatile("st.shared.v2.f32 [%0], {%1,%2};" :: "r"(a), "f"(v0), "f"(v1));
}
DINLINE void cpa16(uint32_t d, const float* s) {
    asm volatile("cp.async.cg.shared.global [%0], [%1], 16;" :: "r"(d), "l"(s));
}
#define CP_COMMIT() asm volatile("cp.async.commit_group;")
#define CP_WAIT0()  asm volatile("cp.async.wait_group 0;")

DINLINE void mma8(float (&d)[4], uint32_t a0, uint32_t a1, uint32_t a2, uint32_t a3,
                  uint32_t b0, uint32_t b1) {
    asm volatile(
        "mma.sync.aligned.m16n8k8.row.col.f32.tf32.tf32.f32 "
        "{%0,%1,%2,%3}, {%4,%5,%6,%7}, {%8,%9}, {%0,%1,%2,%3};"
        : "+f"(d[0]), "+f"(d[1]), "+f"(d[2]), "+f"(d[3])
        : "r"(a0), "r"(a1), "r"(a2), "r"(a3), "r"(b0), "r"(b1));
}

// ======================= geometry =======================
// CTA: 256 thr = 8 warps; tile = 32 rows x 128 w-cols. warp grid 2m x 4n (tile 16x32).
// 8 GEMMs (K=128 each) per CTA, weights single-buffered (4 fills), X in 3 frag slots.
static constexpr uint32_t W_BYTES    = 65536;    // one frag-ordered weight matrix
static constexpr uint32_t SLOT_PITCH = 16640;    // 16384 frag bytes, or 32x130 f32 plane
static constexpr uint32_t OFF_SLOT   = W_BYTES;
static constexpr uint32_t SMEM_TOTAL = W_BYTES + 3 * SLOT_PITCH;  // 115456
#define SLOT(i) (OFF_SLOT + (uint32_t)(i) * SLOT_PITCH)

// Fragment-ordered weights g_Wf[j][kc(16)][pair(8)][lane(32)][4]:
//   e = sub*2+q : value = Wt[w][k], w = pair*16 + sub*8 + lane/4, k = kc*8 + (lane&3) + q*4
// j: 0=W000, 1=W011, 2=W110, 3=W101 (source layout [k][w]); tf32-rounded.
__device__ __align__(16) float g_Wf[4 * 16384];

__global__ void o3tp_prep(const float* __restrict__ W000, const float* __restrict__ W011,
                          const float* __restrict__ W110, const float* __restrict__ W101) {
    int f = blockIdx.x * blockDim.x + threadIdx.x;  // 0..65535
    int j    = f >> 14;
    int r    = f & 16383;
    int kc   = r >> 10;
    int r2   = r & 1023;
    int p    = r2 >> 7;
    int r3   = r2 & 127;
    int lane = r3 >> 2;
    int e    = r3 & 3;
    int sub  = e >> 1;
    int q    = e & 1;
    int w = p * 16 + sub * 8 + (lane >> 2);
    int k = kc * 8 + (lane & 3) + q * 4;
    const float* src = (j == 0) ? W000 : (j == 1) ? W011 : (j == 2) ? W110 : W101;
    g_Wf[f] = __uint_as_float(cvt_tf32(src[k * 128 + w]));
}

// ======================= fills =======================
DINLINE void fill_w(uint32_t sb, int j, int t) {
    const float* src = g_Wf + j * 16384;
    #pragma unroll
    for (int e = 0; e < 16; ++e) {
        int ch = e * 256 + t;
        cpa16(sb + (uint32_t)ch * 16u, src + ch * 4);
    }
}

// frag address of X value (local row r, k) within a slot
DINLINE uint32_t xfrag_addr(uint32_t slot, int r, int k) {
    uint32_t g  = (uint32_t)(r >> 4);
    uint32_t rr = (uint32_t)(r & 15);
    uint32_t ln = (rr & 7) * 4 + (uint32_t)(k & 3);
    uint32_t vl = (rr >> 3) + (uint32_t)((k >> 2) & 1) * 2;
    return slot + g * 8192u + (uint32_t)(k >> 3) * 512u + ln * 16u + vl * 4u;
}

// X0 = x[:, 0:128] -> frag layout in slot0 (tf32-rounded)
DINLINE void fill_x0(uint32_t slot, const float* __restrict__ x, long row0, int n, int t) {
    int r  = t >> 3;
    int c0 = (t & 7) * 16;
    long gr = row0 + r;
    bool v = gr < (long)n;
    const float4* src = (const float4*)(x + gr * 512 + c0);
    #pragma unroll
    for (int m = 0; m < 4; ++m) {
        float4 xv = v ? src[m] : make_float4(0.f, 0.f, 0.f, 0.f);
        int kb = c0 + m * 4;
        sts_b32(xfrag_addr(slot, r, kb + 0), cvt_tf32(xv.x));
        sts_b32(xfrag_addr(slot, r, kb + 1), cvt_tf32(xv.y));
        sts_b32(xfrag_addr(slot, r, kb + 2), cvt_tf32(xv.z));
        sts_b32(xfrag_addr(slot, r, kb + 3), cvt_tf32(xv.w));
    }
}

// X1: one contiguous pass over x[:, 128:512]; de-interleave into 3 frag slots
DINLINE void fill_x1(uint32_t sb, const float* __restrict__ x, long row0, int n, int t) {
    int r  = t >> 3;
    int f0 = (t & 7) * 48;          // multiple of 3
    long gr = row0 + r;
    bool v = gr < (long)n;
    const float4* src = (const float4*)(x + gr * 512 + 128 + f0);
    int u = f0 / 3;
    int i = 0;
    #pragma unroll
    for (int m = 0; m < 12; ++m) {
        float4 xv = v ? src[m] : make_float4(0.f, 0.f, 0.f, 0.f);
        float e[4] = {xv.x, xv.y, xv.z, xv.w};
        #pragma unroll
        for (int c = 0; c < 4; ++c) {
            sts_b32(xfrag_addr(SLOT(i) + sb, r, u), cvt_tf32(e[c]));
            if (++i == 3) { i = 0; ++u; }
        }
    }
}

// ======================= GEMM (32x128 out, K=128) =======================
DINLINE void gemm32(uint32_t xslot, uint32_t wbase, float (&acc)[4][4],
                    int wm, int wn, int lane) {
    const uint32_t xa = xslot + (uint32_t)wm * 8192u + (uint32_t)lane * 16u;
    const uint32_t wb = wbase + (uint32_t)wn * 1024u + (uint32_t)lane * 16u;
    #pragma unroll
    for (int kc = 0; kc < 16; ++kc) {
        uint4 a  = lds128(xa + kc * 512);
        uint4 b0 = lds128(wb + kc * 4096);
        uint4 b1 = lds128(wb + kc * 4096 + 512);
        mma8(acc[0], a.x, a.y, a.z, a.w, b0.x, b0.y);
        mma8(acc[1], a.x, a.y, a.z, a.w, b0.z, b0.w);
        mma8(acc[2], a.x, a.y, a.z, a.w, b1.x, b1.y);
        mma8(acc[3], a.x, a.y, a.z, a.w, b1.z, b1.w);
    }
}

DINLINE void zero4x4(float (&a)[4][4]) {
    #pragma unroll
    for (int s = 0; s < 4; ++s)
        #pragma unroll
        for (int q = 0; q < 4; ++q) a[s][q] = 0.0f;
}

// ======================= main kernel =======================
__global__ void __launch_bounds__(256, 2) o3tp_main(
    const float* __restrict__ x,     // (n, 512)
    const float* __restrict__ y,     // (n, 4)
    const float* __restrict__ bias,  // (128,)
    float* __restrict__ out,         // (n, 512)
    int n)
{
    extern __shared__ char smem[];
    const uint32_t sb = smem_u32(smem);
    const int t    = threadIdx.x;
    const int wid  = t >> 5;
    const int lane = t & 31;
    const int wm   = wid & 1;
    const int wn   = wid >> 1;
    const long row0 = (long)blockIdx.x * 32;

    // ---- prologue fills ----
    fill_x0(SLOT(0) + sb - OFF_SLOT + OFF_SLOT, x, row0, n, t);  // slot0
    fill_w(sb, 0, t);  // W000
    CP_COMMIT();

    // y for this thread's c-frag rows
    const int  ra  = wm * 16 + (lane >> 2);
    const long gra = row0 + ra;
    const long grb = gra + 8;
    const bool va = gra < (long)n;
    const bool vb = grb < (long)n;
    float ya[4] = {0, 0, 0, 0}, yb[4] = {0, 0, 0, 0};
    if (va) { float4 v = *(const float4*)(y + gra * 4); ya[0] = v.x; ya[1] = v.y; ya[2] = v.z; ya[3] = v.w; }
    if (vb) { float4 v = *(const float4*)(y + grb * 4); yb[0] = v.x; yb[1] = v.y; yb[2] = v.z; yb[3] = v.w; }

    float o0[4][4], p011[4][4], cur[4][4];
    zero4x4(o0);

    CP_WAIT0();
    __syncthreads();

    // ---- s0: X0 @ W000 -> fold o0 += y0*cur ----
    zero4x4(cur);
    gemm32(sb + SLOT(0), sb, cur, wm, wn, lane);
    #pragma unroll
    for (int s = 0; s < 4; ++s) {
        o0[s][0] += ya[0] * cur[s][0]; o0[s][1] += ya[0] * cur[s][1];
        o0[s][2] += yb[0] * cur[s][2]; o0[s][3] += yb[0] * cur[s][3];
    }
    __syncthreads();
    fill_w(sb, 1, t);  // W011
    CP_COMMIT(); CP_WAIT0();
    __syncthreads();

    // ---- s1: P011 = X0 @ W011 (retained) ----
    zero4x4(p011);
    gemm32(sb + SLOT(0), sb, p011, wm, wn, lane);
    __syncthreads();
    fill_w(sb, 2, t);                 // W110
    fill_x1(sb, x, row0, n, t);       // X1_0/1/2 -> slots 0/1/2 (overwrites X0)
    CP_COMMIT(); CP_WAIT0();
    __syncthreads();

    // ---- s2..s4: Q_i = X1_i @ W110 -> fold o0 += S3*y1_i*Q_i ----
    #pragma unroll
    for (int i = 0; i < 3; ++i) {
        zero4x4(cur);
        gemm32(sb + SLOT(i), sb, cur, wm, wn, lane);
        const float fa = S3 * ya[1 + i], fb = S3 * yb[1 + i];
        #pragma unroll
        for (int s = 0; s < 4; ++s) {
            o0[s][0] += fa * cur[s][0]; o0[s][1] += fa * cur[s][1];
            o0[s][2] += fb * cur[s][2]; o0[s][3] += fb * cur[s][3];
        }
    }

    // ---- store o0 + bias (coalesced float2) ----
    #pragma unroll
    for (int s = 0; s < 4; ++s) {
        const int w0 = wn * 32 + s * 8 + 2 * (lane & 3);
        const float b0 = __ldg(bias + w0), b1 = __ldg(bias + w0 + 1);
        if (va) { float2 o = make_float2(o0[s][0] + b0, o0[s][1] + b1);
                  *(float2*)(out + gra * 512 + w0) = o; }
        if (vb) { float2 o = make_float2(o0[s][2] + b0, o0[s][3] + b1);
                  *(float2*)(out + grb * 512 + w0) = o; }
    }
    __syncthreads();
    fill_w(sb, 3, t);  // W101
    CP_COMMIT(); CP_WAIT0();
    __syncthreads();

    // ---- s5..s7: R_i = X1_i @ W101 -> stage o1_i = S3*(y1_i*P011 + y0*R_i) ----
    const int rb = ra + 8;
    #pragma unroll
    for (int i = 0; i < 3; ++i) {
        zero4x4(cur);
        gemm32(sb + SLOT(i), sb, cur, wm, wn, lane);
        __syncthreads();  // all warps done reading slot i -> safe to overwrite as plane i
        const uint32_t plane = sb + SLOT(i);
        const float y1a = ya[1 + i], y1b = yb[1 + i];
        #pragma unroll
        for (int s = 0; s < 4; ++s) {
            const int w0 = wn * 32 + s * 8 + 2 * (lane & 3);
            sts_f32x2(plane + ((uint32_t)ra * 130u + (uint32_t)w0) * 4u,
                      S3 * (y1a * p011[s][0] + ya[0] * cur[s][0]),
                      S3 * (y1a * p011[s][1] + ya[0] * cur[s][1]));
            sts_f32x2(plane + ((uint32_t)rb * 130u + (uint32_t)w0) * 4u,
                      S3 * (y1b * p011[s][2] + yb[0] * cur[s][2]),
                      S3 * (y1b * p011[s][3] + yb[0] * cur[s][3]));
        }
    }
    __syncthreads();

    // ---- final: interleave planes -> out[:, 128:512] with STG.128 ----
    {
        const int r  = t >> 3;
        const int c0 = (t & 7) * 48;   // multiple of 3
        const long gr = row0 + r;
        if (gr < (long)n) {
            float* dst = out + gr * 512 + 128 + c0;
            int w = c0 / 3;
            int i = 0;
            #pragma unroll
            for (int m = 0; m < 12; ++m) {
                float4 v;
                float* vp = &v.x;
                #pragma unroll
                for (int c = 0; c < 4; ++c) {
                    vp[c] = lds_f32(sb + SLOT(i) + ((uint32_t)r * 130u + (uint32_t)w) * 4u);
                    if (++i == 3) { i = 0; ++w; }
                }
                *(float4*)(dst + m * 4) = v;
            }
        }
    }
}

// ======================= launch =======================
extern "C" void kernel_launch(void* const* d_in, const int* in_sizes, int n_in,
                              void* d_out, int out_size) {
    const float* x    = (const float*)d_in[0];
    const float* y    = (const float*)d_in[1];
    const float* W000 = (const float*)d_in[2];
    const float* W011 = (const float*)d_in[3];
    const float* W101 = (const float*)d_in[4];
    const float* W110 = (const float*)d_in[5];
    const float* bias = (const float*)d_in[6];

    int n = in_sizes[1] / 4;  // y is (n, 4)
    if (n <= 0) return;

    o3tp_prep<<<256, 256>>>(W000, W011, W110, W101);

    cudaFuncSetAttribute(o3tp_main, cudaFuncAttributeMaxDynamicSharedMemorySize, SMEM_TOTAL);
    int grid = (n + 31) / 32;
    o3tp_main<<<grid, 256, SMEM_TOTAL>>>(x, y, bias, (float*)d_out, n);
}

// round 4
// speedup vs baseline: 1.3808x; 1.0009x over previous
#include <cuda_runtime.h>
#include <cstdint>

#define DINLINE __device__ __forceinline__

static __device__ constexpr float S3 = 0.57735026918962576451f;  // 1/sqrt(3)

// ======================= low-level helpers =======================
DINLINE uint32_t smem_u32(const void* p) {
    uint32_t a;
    asm("{ .reg .u64 t; cvta.to.shared.u64 t, %1; cvt.u32.u64 %0, t; }" : "=r"(a) : "l"(p));
    return a;
}
DINLINE uint32_t cvt_tf32(float f) {
    uint32_t u;
    asm("cvt.rna.tf32.f32 %0, %1;" : "=r"(u) : "f"(f));
    return u;
}
DINLINE uint4 lds128(uint32_t a) {
    uint4 v;
    asm volatile("ld.shared.v4.b32 {%0,%1,%2,%3}, [%4];"
                 : "=r"(v.x), "=r"(v.y), "=r"(v.z), "=r"(v.w) : "r"(a));
    return v;
}
DINLINE float lds_f32(uint32_t a) {
    float v;
    asm volatile("ld.shared.f32 %0, [%1];" : "=f"(v) : "r"(a));
    return v;
}
DINLINE void sts_b32(uint32_t a, uint32_t v) {
    asm volatile("st.shared.b32 [%0], %1;" :: "r"(a), "r"(v));
}
DINLINE void sts_f32x2(uint32_t a, float v0, float v1) {
    asm volatile("st.shared.v2.f32 [%0], {%1,%2};" :: "r"(a), "f"(v0), "f"(v1));
}
DINLINE void cpa16(uint32_t d, const float* s) {
    asm volatile("cp.async.cg.shared.global [%0], [%1], 16;" :: "r"(d), "l"(s));
}
#define CP_COMMIT() asm volatile("cp.async.commit_group;")
#define CP_WAIT0()  asm volatile("cp.async.wait_group 0;")

DINLINE void mma8(float (&d)[4], uint32_t a0, uint32_t a1, uint32_t a2, uint32_t a3,
                  uint32_t b0, uint32_t b1) {
    asm volatile(
        "mma.sync.aligned.m16n8k8.row.col.f32.tf32.tf32.f32 "
        "{%0,%1,%2,%3}, {%4,%5,%6,%7}, {%8,%9}, {%0,%1,%2,%3};"
        : "+f"(d[0]), "+f"(d[1]), "+f"(d[2]), "+f"(d[3])
        : "r"(a0), "r"(a1), "r"(a2), "r"(a3), "r"(b0), "r"(b1));
}

// ======================= geometry =======================
// CTA: 256 thr = 8 warps; tile = 32 rows x 128 w-cols. warp grid 2m x 4n (tile 16x32).
// 8 GEMMs (K=128 each) per CTA, weights single-buffered (4 fills), X in 3 frag slots.
static constexpr uint32_t W_BYTES    = 65536;    // one frag-ordered weight matrix
static constexpr uint32_t SLOT_PITCH = 16640;    // 16384 frag bytes, or 32x130 f32 plane
static constexpr uint32_t OFF_SLOT   = W_BYTES;
static constexpr uint32_t SMEM_TOTAL = W_BYTES + 3 * SLOT_PITCH;  // 115456
#define SLOT(i) (OFF_SLOT + (uint32_t)(i) * SLOT_PITCH)

// Fragment-ordered weights g_Wf[j][kc(16)][pair(8)][lane(32)][4]:
//   e = sub*2+q : value = Wt[w][k], w = pair*16 + sub*8 + lane/4, k = kc*8 + (lane&3) + q*4
// j: 0=W000, 1=W011, 2=W110, 3=W101 (source layout [k][w]); tf32-rounded.
__device__ __align__(16) float g_Wf[4 * 16384];

__global__ void o3tp_prep(const float* __restrict__ W000, const float* __restrict__ W011,
                          const float* __restrict__ W110, const float* __restrict__ W101) {
    int f = blockIdx.x * blockDim.x + threadIdx.x;  // 0..65535
    int j    = f >> 14;
    int r    = f & 16383;
    int kc   = r >> 10;
    int r2   = r & 1023;
    int p    = r2 >> 7;
    int r3   = r2 & 127;
    int lane = r3 >> 2;
    int e    = r3 & 3;
    int sub  = e >> 1;
    int q    = e & 1;
    int w = p * 16 + sub * 8 + (lane >> 2);
    int k = kc * 8 + (lane & 3) + q * 4;
    const float* src = (j == 0) ? W000 : (j == 1) ? W011 : (j == 2) ? W110 : W101;
    g_Wf[f] = __uint_as_float(cvt_tf32(src[k * 128 + w]));
}

// ======================= fills =======================
DINLINE void fill_w(uint32_t sb, int j, int t) {
    const float* src = g_Wf + j * 16384;
    #pragma unroll
    for (int e = 0; e < 16; ++e) {
        int ch = e * 256 + t;
        cpa16(sb + (uint32_t)ch * 16u, src + ch * 4);
    }
}

// frag address of X value (local row r, k) within a slot
DINLINE uint32_t xfrag_addr(uint32_t slot, int r, int k) {
    uint32_t g  = (uint32_t)(r >> 4);
    uint32_t rr = (uint32_t)(r & 15);
    uint32_t ln = (rr & 7) * 4 + (uint32_t)(k & 3);
    uint32_t vl = (rr >> 3) + (uint32_t)((k >> 2) & 1) * 2;
    return slot + g * 8192u + (uint32_t)(k >> 3) * 512u + ln * 16u + vl * 4u;
}

// X0 = x[:, 0:128] -> frag layout in slot0 (tf32-rounded)
DINLINE void fill_x0(uint32_t slot, const float* __restrict__ x, long row0, int n, int t) {
    int r  = t >> 3;
    int c0 = (t & 7) * 16;
    long gr = row0 + r;
    bool v = gr < (long)n;
    const float4* src = (const float4*)(x + gr * 512 + c0);
    #pragma unroll
    for (int m = 0; m < 4; ++m) {
        float4 xv = v ? src[m] : make_float4(0.f, 0.f, 0.f, 0.f);
        int kb = c0 + m * 4;
        sts_b32(xfrag_addr(slot, r, kb + 0), cvt_tf32(xv.x));
        sts_b32(xfrag_addr(slot, r, kb + 1), cvt_tf32(xv.y));
        sts_b32(xfrag_addr(slot, r, kb + 2), cvt_tf32(xv.z));
        sts_b32(xfrag_addr(slot, r, kb + 3), cvt_tf32(xv.w));
    }
}

// X1: one contiguous pass over x[:, 128:512]; de-interleave into 3 frag slots
DINLINE void fill_x1(uint32_t sb, const float* __restrict__ x, long row0, int n, int t) {
    int r  = t >> 3;
    int f0 = (t & 7) * 48;          // multiple of 3
    long gr = row0 + r;
    bool v = gr < (long)n;
    const float4* src = (const float4*)(x + gr * 512 + 128 + f0);
    int u = f0 / 3;
    int i = 0;
    #pragma unroll
    for (int m = 0; m < 12; ++m) {
        float4 xv = v ? src[m] : make_float4(0.f, 0.f, 0.f, 0.f);
        float e[4] = {xv.x, xv.y, xv.z, xv.w};
        #pragma unroll
        for (int c = 0; c < 4; ++c) {
            sts_b32(xfrag_addr(SLOT(i) + sb, r, u), cvt_tf32(e[c]));
            if (++i == 3) { i = 0; ++u; }
        }
    }
}

// ======================= GEMM (32x128 out, K=128) =======================
DINLINE void gemm32(uint32_t xslot, uint32_t wbase, float (&acc)[4][4],
                    int wm, int wn, int lane) {
    const uint32_t xa = xslot + (uint32_t)wm * 8192u + (uint32_t)lane * 16u;
    const uint32_t wb = wbase + (uint32_t)wn * 1024u + (uint32_t)lane * 16u;
    #pragma unroll
    for (int kc = 0; kc < 16; ++kc) {
        uint4 a  = lds128(xa + kc * 512);
        uint4 b0 = lds128(wb + kc * 4096);
        uint4 b1 = lds128(wb + kc * 4096 + 512);
        mma8(acc[0], a.x, a.y, a.z, a.w, b0.x, b0.y);
        mma8(acc[1], a.x, a.y, a.z, a.w, b0.z, b0.w);
        mma8(acc[2], a.x, a.y, a.z, a.w, b1.x, b1.y);
        mma8(acc[3], a.x, a.y, a.z, a.w, b1.z, b1.w);
    }
}

DINLINE void zero4x4(float (&a)[4][4]) {
    #pragma unroll
    for (int s = 0; s < 4; ++s)
        #pragma unroll
        for (int q = 0; q < 4; ++q) a[s][q] = 0.0f;
}

// ======================= main kernel =======================
__global__ void __launch_bounds__(256, 2) o3tp_main(
    const float* __restrict__ x,     // (n, 512)
    const float* __restrict__ y,     // (n, 4)
    const float* __restrict__ bias,  // (128,)
    float* __restrict__ out,         // (n, 512)
    int n)
{
    extern __shared__ char smem[];
    const uint32_t sb = smem_u32(smem);
    const int t    = threadIdx.x;
    const int wid  = t >> 5;
    const int lane = t & 31;
    const int wm   = wid & 1;
    const int wn   = wid >> 1;
    const long row0 = (long)blockIdx.x * 32;

    // ---- prologue fills ----
    fill_x0(SLOT(0) + sb - OFF_SLOT + OFF_SLOT, x, row0, n, t);  // slot0
    fill_w(sb, 0, t);  // W000
    CP_COMMIT();

    // y for this thread's c-frag rows
    const int  ra  = wm * 16 + (lane >> 2);
    const long gra = row0 + ra;
    const long grb = gra + 8;
    const bool va = gra < (long)n;
    const bool vb = grb < (long)n;
    float ya[4] = {0, 0, 0, 0}, yb[4] = {0, 0, 0, 0};
    if (va) { float4 v = *(const float4*)(y + gra * 4); ya[0] = v.x; ya[1] = v.y; ya[2] = v.z; ya[3] = v.w; }
    if (vb) { float4 v = *(const float4*)(y + grb * 4); yb[0] = v.x; yb[1] = v.y; yb[2] = v.z; yb[3] = v.w; }

    float o0[4][4], p011[4][4], cur[4][4];
    zero4x4(o0);

    CP_WAIT0();
    __syncthreads();

    // ---- s0: X0 @ W000 -> fold o0 += y0*cur ----
    zero4x4(cur);
    gemm32(sb + SLOT(0), sb, cur, wm, wn, lane);
    #pragma unroll
    for (int s = 0; s < 4; ++s) {
        o0[s][0] += ya[0] * cur[s][0]; o0[s][1] += ya[0] * cur[s][1];
        o0[s][2] += yb[0] * cur[s][2]; o0[s][3] += yb[0] * cur[s][3];
    }
    __syncthreads();
    fill_w(sb, 1, t);  // W011
    CP_COMMIT(); CP_WAIT0();
    __syncthreads();

    // ---- s1: P011 = X0 @ W011 (retained) ----
    zero4x4(p011);
    gemm32(sb + SLOT(0), sb, p011, wm, wn, lane);
    __syncthreads();
    fill_w(sb, 2, t);                 // W110
    fill_x1(sb, x, row0, n, t);       // X1_0/1/2 -> slots 0/1/2 (overwrites X0)
    CP_COMMIT(); CP_WAIT0();
    __syncthreads();

    // ---- s2..s4: Q_i = X1_i @ W110 -> fold o0 += S3*y1_i*Q_i ----
    #pragma unroll
    for (int i = 0; i < 3; ++i) {
        zero4x4(cur);
        gemm32(sb + SLOT(i), sb, cur, wm, wn, lane);
        const float fa = S3 * ya[1 + i], fb = S3 * yb[1 + i];
        #pragma unroll
        for (int s = 0; s < 4; ++s) {
            o0[s][0] += fa * cur[s][0]; o0[s][1] += fa * cur[s][1];
            o0[s][2] += fb * cur[s][2]; o0[s][3] += fb * cur[s][3];
        }
    }

    // ---- store o0 + bias (coalesced float2) ----
    #pragma unroll
    for (int s = 0; s < 4; ++s) {
        const int w0 = wn * 32 + s * 8 + 2 * (lane & 3);
        const float b0 = __ldg(bias + w0), b1 = __ldg(bias + w0 + 1);
        if (va) { float2 o = make_float2(o0[s][0] + b0, o0[s][1] + b1);
                  *(float2*)(out + gra * 512 + w0) = o; }
        if (vb) { float2 o = make_float2(o0[s][2] + b0, o0[s][3] + b1);
                  *(float2*)(out + grb * 512 + w0) = o; }
    }
    __syncthreads();
    fill_w(sb, 3, t);  // W101
    CP_COMMIT(); CP_WAIT0();
    __syncthreads();

    // ---- s5..s7: R_i = X1_i @ W101 -> stage o1_i = S3*(y1_i*P011 + y0*R_i) ----
    const int rb = ra + 8;
    #pragma unroll
    for (int i = 0; i < 3; ++i) {
        zero4x4(cur);
        gemm32(sb + SLOT(i), sb, cur, wm, wn, lane);
        __syncthreads();  // all warps done reading slot i -> safe to overwrite as plane i
        const uint32_t plane = sb + SLOT(i);
        const float y1a = ya[1 + i], y1b = yb[1 + i];
        #pragma unroll
        for (int s = 0; s < 4; ++s) {
            const int w0 = wn * 32 + s * 8 + 2 * (lane & 3);
            sts_f32x2(plane + ((uint32_t)ra * 130u + (uint32_t)w0) * 4u,
                      S3 * (y1a * p011[s][0] + ya[0] * cur[s][0]),
                      S3 * (y1a * p011[s][1] + ya[0] * cur[s][1]));
            sts_f32x2(plane + ((uint32_t)rb * 130u + (uint32_t)w0) * 4u,
                      S3 * (y1b * p011[s][2] + yb[0] * cur[s][2]),
                      S3 * (y1b * p011[s][3] + yb[0] * cur[s][3]));
        }
    }
    __syncthreads();

    // ---- final: interleave planes -> out[:, 128:512] with STG.128 ----
    {
        const int r  = t >> 3;
        const int c0 = (t & 7) * 48;   // multiple of 3
        const long gr = row0 + r;
        if (gr < (long)n) {
            float* dst = out + gr * 512 + 128 + c0;
            int w = c0 / 3;
            int i = 0;
            #pragma unroll
            for (int m = 0; m < 12; ++m) {
                float4 v;
                float* vp = &v.x;
                #pragma unroll
                for (int c = 0; c < 4; ++c) {
                    vp[c] = lds_f32(sb + SLOT(i) + ((uint32_t)r * 130u + (uint32_t)w) * 4u);
                    if (++i == 3) { i = 0; ++w; }
                }
                *(float4*)(dst + m * 4) = v;
            }
        }
    }
}

// ======================= launch =======================
extern "C" void kernel_launch(void* const* d_in, const int* in_sizes, int n_in,
                              void* d_out, int out_size) {
    const float* x    = (const float*)d_in[0];
    const float* y    = (const float*)d_in[1];
    const float* W000 = (const float*)d_in[2];
    const float* W011 = (const float*)d_in[3];
    const float* W101 = (const float*)d_in[4];
    const float* W110 = (const float*)d_in[5];
    const float* bias = (const float*)d_in[6];

    int n = in_sizes[1] / 4;  // y is (n, 4)
    if (n <= 0) return;

    o3tp_prep<<<256, 256>>>(W000, W011, W110, W101);

    cudaFuncSetAttribute(o3tp_main, cudaFuncAttributeMaxDynamicSharedMemorySize, SMEM_TOTAL);
    int grid = (n + 31) / 32;
    o3tp_main<<<grid, 256, SMEM_TOTAL>>>(x, y, bias, (float*)d_out, n);
}

// round 5
// speedup vs baseline: 2.5016x; 1.8117x over previous
#include <cuda_runtime.h>
#include <cuda_fp16.h>
#include <cstdint>

#define DINLINE __device__ __forceinline__
static __device__ constexpr float S3 = 0.57735026918962576451f;  // 1/sqrt(3)

// ======================= low-level helpers =======================
DINLINE uint32_t smem_u32(const void* p) {
    uint32_t a;
    asm("{ .reg .u64 t; cvta.to.shared.u64 t, %1; cvt.u32.u64 %0, t; }" : "=r"(a) : "l"(p));
    return a;
}
DINLINE void sts64(uint32_t a, uint32_t lo, uint32_t hi) {
    asm volatile("st.shared.v2.b32 [%0], {%1,%2};" :: "r"(a), "r"(lo), "r"(hi));
}
DINLINE void sts32(uint32_t a, uint32_t v) {
    asm volatile("st.shared.b32 [%0], %1;" :: "r"(a), "r"(v));
}
DINLINE uint32_t lds32(uint32_t a) {
    uint32_t v;
    asm volatile("ld.shared.b32 %0, [%1];" : "=r"(v) : "r"(a));
    return v;
}
DINLINE void cpa16(uint32_t d, const void* s) {
    asm volatile("cp.async.cg.shared.global [%0], [%1], 16;" :: "r"(d), "l"(s));
}
#define CP_COMMIT() asm volatile("cp.async.commit_group;")
#define CP_WAIT0()  asm volatile("cp.async.wait_group 0;")

DINLINE void ldmx4(uint32_t (&v)[4], uint32_t a) {
    asm volatile("ldmatrix.sync.aligned.m8n8.x4.shared.b16 {%0,%1,%2,%3}, [%4];"
                 : "=r"(v[0]), "=r"(v[1]), "=r"(v[2]), "=r"(v[3]) : "r"(a));
}
DINLINE void mmaf16(float (&d)[4], const uint32_t (&a)[4], uint32_t b0, uint32_t b1) {
    asm volatile(
        "mma.sync.aligned.m16n8k16.row.col.f32.f16.f16.f32 "
        "{%0,%1,%2,%3}, {%4,%5,%6,%7}, {%8,%9}, {%0,%1,%2,%3};"
        : "+f"(d[0]), "+f"(d[1]), "+f"(d[2]), "+f"(d[3])
        : "r"(a[0]), "r"(a[1]), "r"(a[2]), "r"(a[3]), "r"(b0), "r"(b1));
}
DINLINE uint32_t h2u(__half2 h) { return *reinterpret_cast<uint32_t*>(&h); }
DINLINE __half2  u2h(uint32_t u) { return *reinterpret_cast<__half2*>(&u); }
DINLINE uint32_t pack2(float a, float b) { return h2u(__floats2half2_rn(a, b)); }

// ======================= geometry =======================
// CTA 256 thr = 8 warps; tile = 64 rows x 128 w-cols; warp tile 32x32.
// smem rows: 128 f16 = 256 B = 16 chunks of 16 B, XOR-swizzled: chunk' = c ^ (row&7).
static constexpr uint32_t W_BYTES = 32768;
static constexpr uint32_t SLOT_B  = 16896;                 // 16 KB data (+pad for 132-pitch planes)
static constexpr uint32_t OFF_X0  = W_BYTES;
#define OFF_S(i) (W_BYTES + SLOT_B + (uint32_t)(i) * SLOT_B)
static constexpr uint32_t SMEM_TOTAL = W_BYTES + 4 * SLOT_B;  // 100352

// Weights in smem-image order (swizzle pre-applied): g_Wh[j][row n(128)][chunk'(16)][e(8)]
// j: 0=W000, 1=W011, 2=W110, 3=W101; value = W_src[k][n], k = (chunk'^(n&7))*8 + e.
__device__ __align__(16) __half g_Wh[4 * 16384];

__global__ void o3tp_prep(const float* __restrict__ W000, const float* __restrict__ W011,
                          const float* __restrict__ W110, const float* __restrict__ W101) {
    int f = blockIdx.x * blockDim.x + threadIdx.x;  // 0..65535
    int j = f >> 14, r = (f >> 7) & 127, cp = (f >> 3) & 15, e = f & 7;
    int k = ((cp ^ (r & 7)) << 3) + e;
    const float* src = (j == 0) ? W000 : (j == 1) ? W011 : (j == 2) ? W110 : W101;
    g_Wh[f] = __float2half_rn(src[k * 128 + r]);
}

// ======================= fills =======================
DINLINE void fill_w(uint32_t wb, int j, int t) {
    const __half* src = g_Wh + j * 16384;
    #pragma unroll
    for (int e = 0; e < 8; ++e) {
        int ch = e * 256 + t;
        cpa16(wb + (uint32_t)ch * 16u, src + ch * 8);
    }
}
// X0 = x[:, 0:128] -> f16 swizzled rows
DINLINE void fill_x0(uint32_t slot, const float* __restrict__ x, long row0, int n, int t) {
    int r = t >> 2, q = t & 3;
    long gr = row0 + r;
    bool v = gr < (long)n;
    const float4* src = (const float4*)(x + gr * 512 + q * 32);
    uint32_t rb = slot + (uint32_t)r * 256u, s = (uint32_t)(r & 7);
    #pragma unroll
    for (int m = 0; m < 8; ++m) {
        float4 xv = v ? src[m] : make_float4(0.f, 0.f, 0.f, 0.f);
        uint32_t k0 = (uint32_t)(q * 32 + m * 4);
        sts64(rb + (((k0 >> 3) ^ s) << 4) + ((k0 >> 2) & 1) * 8,
              pack2(xv.x, xv.y), pack2(xv.z, xv.w));
    }
}
// X1: one contiguous pass over x[:, 128:512]; de-interleave into 3 f16 slots
DINLINE void fill_x1(uint32_t sb, const float* __restrict__ x, long row0, int n, int t) {
    int r = t >> 2, q = t & 3;
    long gr = row0 + r;
    bool v = gr < (long)n;
    const float4* src = (const float4*)(x + gr * 512 + 128 + q * 96);
    uint32_t rb = (uint32_t)r * 256u, s = (uint32_t)(r & 7);
    #pragma unroll
    for (int mm = 0; mm < 8; ++mm) {
        float a[12];
        #pragma unroll
        for (int j = 0; j < 3; ++j) {
            float4 xv = v ? src[mm * 3 + j] : make_float4(0.f, 0.f, 0.f, 0.f);
            a[j * 4 + 0] = xv.x; a[j * 4 + 1] = xv.y; a[j * 4 + 2] = xv.z; a[j * 4 + 3] = xv.w;
        }
        uint32_t u0 = (uint32_t)(q * 32 + mm * 4);
        uint32_t off = rb + (((u0 >> 3) ^ s) << 4) + ((u0 >> 2) & 1) * 8;
        #pragma unroll
        for (int i = 0; i < 3; ++i)
            sts64(sb + OFF_S(i) + off, pack2(a[i], a[i + 3]), pack2(a[i + 6], a[i + 9]));
    }
}

// ======================= GEMM (64x128 out, K=128) =======================
DINLINE void gemm64(uint32_t xslot, uint32_t wb, float (&acc)[2][4][4],
                    int wm, int wn, int lane) {
    const uint32_t rA = (uint32_t)(wm * 32 + (lane & 15));
    const uint32_t cA = (uint32_t)((lane >> 4) & 1);
    const uint32_t sA = rA & 7;
    const uint32_t bA0 = xslot + rA * 256u, bA1 = bA0 + 4096u;
    const uint32_t rB = (uint32_t)(wn * 32 + (lane & 7) + (((lane >> 4) & 1) << 3));
    const uint32_t cB = (uint32_t)((lane >> 3) & 1);
    const uint32_t sB = rB & 7;
    const uint32_t bB0 = wb + rB * 256u, bB1 = bB0 + 4096u;
    #pragma unroll
    for (int kc = 0; kc < 8; ++kc) {
        uint32_t a0[4], a1[4], b0[4], b1[4];
        uint32_t ka = (((((uint32_t)kc << 1) | cA) ^ sA) << 4);
        uint32_t kb = (((((uint32_t)kc << 1) | cB) ^ sB) << 4);
        ldmx4(a0, bA0 + ka); ldmx4(a1, bA1 + ka);
        ldmx4(b0, bB0 + kb); ldmx4(b1, bB1 + kb);
        mmaf16(acc[0][0], a0, b0[0], b0[1]); mmaf16(acc[0][1], a0, b0[2], b0[3]);
        mmaf16(acc[0][2], a0, b1[0], b1[1]); mmaf16(acc[0][3], a0, b1[2], b1[3]);
        mmaf16(acc[1][0], a1, b0[0], b0[1]); mmaf16(acc[1][1], a1, b0[2], b0[3]);
        mmaf16(acc[1][2], a1, b1[0], b1[1]); mmaf16(acc[1][3], a1, b1[2], b1[3]);
    }
}
DINLINE void zacc(float (&a)[2][4][4]) {
    #pragma unroll
    for (int m = 0; m < 2; ++m)
        #pragma unroll
        for (int g = 0; g < 4; ++g)
            #pragma unroll
            for (int e = 0; e < 4; ++e) a[m][g][e] = 0.0f;
}

// ======================= main kernel =======================
__global__ void __launch_bounds__(256, 2) o3tp_main(
    const float* __restrict__ x, const float* __restrict__ y,
    const float* __restrict__ bias, float* __restrict__ out, int n)
{
    extern __shared__ char smem[];
    const uint32_t sb = smem_u32(smem);
    const int t = threadIdx.x, lane = t & 31, wid = t >> 5;
    const int wm = wid & 1, wn = wid >> 1;
    const long row0 = (long)blockIdx.x * 64;

    fill_x0(sb + OFF_X0, x, row0, n, t);
    fill_w(sb, 0, t); CP_COMMIT();

    // per-thread c-frag rows & y values: rows rl(mf), rl+8
    int  rl[2];  long gr0[2];  bool va[2], vb[2];
    float yv[2][2][4];
    #pragma unroll
    for (int mf = 0; mf < 2; ++mf) {
        rl[mf] = wm * 32 + mf * 16 + (lane >> 2);
        gr0[mf] = row0 + rl[mf];
        va[mf] = gr0[mf] < (long)n;
        vb[mf] = gr0[mf] + 8 < (long)n;
        #pragma unroll
        for (int e = 0; e < 4; ++e) { yv[mf][0][e] = 0.f; yv[mf][1][e] = 0.f; }
        if (va[mf]) { float4 v = *(const float4*)(y + gr0[mf] * 4);
            yv[mf][0][0] = v.x; yv[mf][0][1] = v.y; yv[mf][0][2] = v.z; yv[mf][0][3] = v.w; }
        if (vb[mf]) { float4 v = *(const float4*)(y + (gr0[mf] + 8) * 4);
            yv[mf][1][0] = v.x; yv[mf][1][1] = v.y; yv[mf][1][2] = v.z; yv[mf][1][3] = v.w; }
    }

    float o0[2][4][4], cur[2][4][4];
    zacc(o0);
    CP_WAIT0(); __syncthreads();

    // ---- s0: X0 @ W000 -> o0 += y0*cur ----
    zacc(cur); gemm64(sb + OFF_X0, sb, cur, wm, wn, lane);
    #pragma unroll
    for (int mf = 0; mf < 2; ++mf)
        #pragma unroll
        for (int g = 0; g < 4; ++g) {
            o0[mf][g][0] += yv[mf][0][0] * cur[mf][g][0];
            o0[mf][g][1] += yv[mf][0][0] * cur[mf][g][1];
            o0[mf][g][2] += yv[mf][1][0] * cur[mf][g][2];
            o0[mf][g][3] += yv[mf][1][0] * cur[mf][g][3];
        }
    __syncthreads();
    fill_w(sb, 1, t); CP_COMMIT(); CP_WAIT0(); __syncthreads();

    // ---- s1: P011 = X0 @ W011 -> stage f16 into X0 region (pitch 132 h) ----
    zacc(cur); gemm64(sb + OFF_X0, sb, cur, wm, wn, lane);
    __syncthreads();  // X0 + W dead
    #pragma unroll
    for (int mf = 0; mf < 2; ++mf)
        #pragma unroll
        for (int g = 0; g < 4; ++g) {
            uint32_t w0 = (uint32_t)(wn * 32 + g * 8 + 2 * (lane & 3));
            sts32(sb + OFF_X0 + ((uint32_t)rl[mf] * 132u + w0) * 2u,
                  pack2(cur[mf][g][0], cur[mf][g][1]));
            sts32(sb + OFF_X0 + ((uint32_t)(rl[mf] + 8) * 132u + w0) * 2u,
                  pack2(cur[mf][g][2], cur[mf][g][3]));
        }
    fill_w(sb, 2, t);
    fill_x1(sb, x, row0, n, t);
    CP_COMMIT(); CP_WAIT0(); __syncthreads();

    // ---- s2-4: Q_i = X1_i @ W110 -> o0 += S3*y1_i*Q_i ----
    #pragma unroll 1
    for (int i = 0; i < 3; ++i) {
        zacc(cur); gemm64(sb + OFF_S(i), sb, cur, wm, wn, lane);
        #pragma unroll
        for (int mf = 0; mf < 2; ++mf) {
            const float fa = S3 * yv[mf][0][1 + i], fb = S3 * yv[mf][1][1 + i];
            #pragma unroll
            for (int g = 0; g < 4; ++g) {
                o0[mf][g][0] += fa * cur[mf][g][0];
                o0[mf][g][1] += fa * cur[mf][g][1];
                o0[mf][g][2] += fb * cur[mf][g][2];
                o0[mf][g][3] += fb * cur[mf][g][3];
            }
        }
    }
    // ---- store o0 + bias (coalesced float2) ----
    #pragma unroll
    for (int mf = 0; mf < 2; ++mf)
        #pragma unroll
        for (int g = 0; g < 4; ++g) {
            const int w0 = wn * 32 + g * 8 + 2 * (lane & 3);
            const float b0 = __ldg(bias + w0), b1 = __ldg(bias + w0 + 1);
            if (va[mf]) { float2 o = make_float2(o0[mf][g][0] + b0, o0[mf][g][1] + b1);
                          *(float2*)(out + gr0[mf] * 512 + w0) = o; }
            if (vb[mf]) { float2 o = make_float2(o0[mf][g][2] + b0, o0[mf][g][3] + b1);
                          *(float2*)(out + (gr0[mf] + 8) * 512 + w0) = o; }
        }
    __syncthreads();
    fill_w(sb, 3, t); CP_COMMIT(); CP_WAIT0(); __syncthreads();

    // ---- s5-7: R_i = X1_i @ W101 -> plane_i = f16( S3*(y1_i*P011 + y0*R_i) ) ----
    #pragma unroll 1
    for (int i = 0; i < 3; ++i) {
        zacc(cur); gemm64(sb + OFF_S(i), sb, cur, wm, wn, lane);
        __syncthreads();  // all warps done reading slot i
        #pragma unroll
        for (int mf = 0; mf < 2; ++mf) {
            const float y1a = yv[mf][0][1 + i], y0a = yv[mf][0][0];
            const float y1b = yv[mf][1][1 + i], y0b = yv[mf][1][0];
            #pragma unroll
            for (int g = 0; g < 4; ++g) {
                uint32_t w0 = (uint32_t)(wn * 32 + g * 8 + 2 * (lane & 3));
                uint32_t pa = sb + OFF_X0 + ((uint32_t)rl[mf] * 132u + w0) * 2u;
                float2 p0 = __half22float2(u2h(lds32(pa)));
                float2 p1 = __half22float2(u2h(lds32(pa + 2112u)));  // +8 rows * 132 * 2
                sts32(sb + OFF_S(i) + ((uint32_t)rl[mf] * 132u + w0) * 2u,
                      pack2(S3 * (y1a * p0.x + y0a * cur[mf][g][0]),
                            S3 * (y1a * p0.y + y0a * cur[mf][g][1])));
                sts32(sb + OFF_S(i) + ((uint32_t)(rl[mf] + 8) * 132u + w0) * 2u,
                      pack2(S3 * (y1b * p1.x + y0b * cur[mf][g][2]),
                            S3 * (y1b * p1.y + y0b * cur[mf][g][3])));
            }
        }
    }
    __syncthreads();

    // ---- final: interleave planes -> out[:, 128:512], STG.128 ----
    {
        const int r = t >> 2, q = t & 3;
        const long gr = row0 + r;
        if (gr < (long)n) {
            float* dst = out + gr * 512 + 128 + q * 96;
            const uint32_t pb = (uint32_t)r * 264u;
            #pragma unroll
            for (int mm = 0; mm < 8; ++mm) {
                const uint32_t w0 = (uint32_t)(q * 32 + mm * 4);
                float p[3][4];
                #pragma unroll
                for (int i = 0; i < 3; ++i) {
                    uint32_t a = sb + OFF_S(i) + pb + w0 * 2u;
                    float2 lo = __half22float2(u2h(lds32(a)));
                    float2 hi = __half22float2(u2h(lds32(a + 4u)));
                    p[i][0] = lo.x; p[i][1] = lo.y; p[i][2] = hi.x; p[i][3] = hi.y;
                }
                float4 f0 = make_float4(p[0][0], p[1][0], p[2][0], p[0][1]);
                float4 f1 = make_float4(p[1][1], p[2][1], p[0][2], p[1][2]);
                float4 f2 = make_float4(p[2][2], p[0][3], p[1][3], p[2][3]);
                *(float4*)(dst + mm * 12)     = f0;
                *(float4*)(dst + mm * 12 + 4) = f1;
                *(float4*)(dst + mm * 12 + 8) = f2;
            }
        }
    }
}

// ======================= launch =======================
extern "C" void kernel_launch(void* const* d_in, const int* in_sizes, int n_in,
                              void* d_out, int out_size) {
    const float* x    = (const float*)d_in[0];
    const float* y    = (const float*)d_in[1];
    const float* W000 = (const float*)d_in[2];
    const float* W011 = (const float*)d_in[3];
    const float* W101 = (const float*)d_in[4];
    const float* W110 = (const float*)d_in[5];
    const float* bias = (const float*)d_in[6];

    int n = in_sizes[1] / 4;  // y is (n, 4)
    if (n <= 0) return;

    o3tp_prep<<<256, 256>>>(W000, W011, W110, W101);

    cudaFuncSetAttribute(o3tp_main, cudaFuncAttributeMaxDynamicSharedMemorySize, SMEM_TOTAL);
    int grid = (n + 63) / 64;
    o3tp_main<<<grid, 256, SMEM_TOTAL>>>(x, y, bias, (float*)d_out, n);
}

// round 6
// speedup vs baseline: 2.9491x; 1.1789x over previous
#include <cuda_runtime.h>
#include <cuda_fp16.h>
#include <cstdint>

#define DINLINE __device__ __forceinline__
static __device__ constexpr float S3 = 0.57735026918962576451f;  // 1/sqrt(3)

// ======================= low-level helpers =======================
DINLINE uint32_t smem_u32(const void* p) {
    uint32_t a;
    asm("{ .reg .u64 t; cvta.to.shared.u64 t, %1; cvt.u32.u64 %0, t; }" : "=r"(a) : "l"(p));
    return a;
}
DINLINE void sts64(uint32_t a, uint32_t lo, uint32_t hi) {
    asm volatile("st.shared.v2.b32 [%0], {%1,%2};" :: "r"(a), "r"(lo), "r"(hi));
}
DINLINE void sts32(uint32_t a, uint32_t v) {
    asm volatile("st.shared.b32 [%0], %1;" :: "r"(a), "r"(v));
}
DINLINE uint32_t lds32(uint32_t a) {
    uint32_t v;
    asm volatile("ld.shared.b32 %0, [%1];" : "=r"(v) : "r"(a));
    return v;
}
DINLINE void ldmx4(uint32_t (&v)[4], uint32_t a) {
    asm volatile("ldmatrix.sync.aligned.m8n8.x4.shared.b16 {%0,%1,%2,%3}, [%4];"
                 : "=r"(v[0]), "=r"(v[1]), "=r"(v[2]), "=r"(v[3]) : "r"(a));
}
DINLINE void mmaf16(float (&d)[4], const uint32_t (&a)[4], uint32_t b0, uint32_t b1) {
    asm volatile(
        "mma.sync.aligned.m16n8k16.row.col.f32.f16.f16.f32 "
        "{%0,%1,%2,%3}, {%4,%5,%6,%7}, {%8,%9}, {%0,%1,%2,%3};"
        : "+f"(d[0]), "+f"(d[1]), "+f"(d[2]), "+f"(d[3])
        : "r"(a[0]), "r"(a[1]), "r"(a[2]), "r"(a[3]), "r"(b0), "r"(b1));
}
DINLINE uint32_t h2u(__half2 h) { return *reinterpret_cast<uint32_t*>(&h); }
DINLINE __half2  u2h(uint32_t u) { return *reinterpret_cast<__half2*>(&u); }
DINLINE uint32_t pack2(float a, float b) { return h2u(__floats2half2_rn(a, b)); }
DINLINE uint32_t hmul2u(uint32_t a, uint32_t b) { return h2u(__hmul2(u2h(a), u2h(b))); }

// ======================= geometry =======================
// CTA 256 thr = 8 warps; tile 64 rows x 128 w-cols; warp tile 32x32 (grid 2m x 4n).
// X rows in smem: 128 f16 = 256 B = 16 chunks of 16 B, XOR swizzle chunk' = c ^ (row&7).
static constexpr uint32_t SLOT_B = 16896;   // raw X 16384 B; as plane 64 x 132h x 2B
#define SLOT(i) ((uint32_t)(i) * SLOT_B)
static constexpr uint32_t SMEM_TOTAL = 3 * SLOT_B;  // 50688

// Fragment-ordered global weights for direct LDG:
// g_Wb[j][wn(4)][kc(8)][lane(32)][e(8)]  (u32 = half2)
//   n = wn*32 + ((e>>1)&1)*8 + ((e>>2)&1)*16 + (lane>>2)
//   k = kc*16 + (e&1)*8 + 2*(lane&3);  value = half2(W[k][n], W[k+1][n])
// j: 0=W000, 1=W011, 2=W110, 3=W101 (source [k][n] = src[k*128+n])
__device__ __align__(16) uint32_t g_Wb[4 * 8192];

__global__ void o3tp_prep(const float* __restrict__ W000, const float* __restrict__ W011,
                          const float* __restrict__ W110, const float* __restrict__ W101) {
    int idx = blockIdx.x * blockDim.x + threadIdx.x;  // 0..32767
    int e = idx & 7, lane = (idx >> 3) & 31, kc = (idx >> 8) & 7;
    int wn = (idx >> 11) & 3, j = idx >> 13;
    int n = wn * 32 + ((e >> 1) & 1) * 8 + ((e >> 2) & 1) * 16 + (lane >> 2);
    int k = kc * 16 + (e & 1) * 8 + 2 * (lane & 3);
    const float* src = (j == 0) ? W000 : (j == 1) ? W011 : (j == 2) ? W110 : W101;
    g_Wb[idx] = pack2(src[k * 128 + n], src[(k + 1) * 128 + n]);
}

// ======================= X fills (f16 swizzled rows) =======================
DINLINE void fill_x0(uint32_t slot, const float* __restrict__ x, long row0, int n, int t) {
    int r = t >> 2, q = t & 3;
    long gr = row0 + r;
    bool v = gr < (long)n;
    const float4* src = (const float4*)(x + gr * 512 + q * 32);
    uint32_t rb = slot + (uint32_t)r * 256u, s = (uint32_t)(r & 7);
    #pragma unroll
    for (int m = 0; m < 8; ++m) {
        float4 xv = v ? src[m] : make_float4(0.f, 0.f, 0.f, 0.f);
        uint32_t k0 = (uint32_t)(q * 32 + m * 4);
        sts64(rb + (((k0 >> 3) ^ s) << 4) + ((k0 >> 2) & 1) * 8,
              pack2(xv.x, xv.y), pack2(xv.z, xv.w));
    }
}
DINLINE void fill_x1(uint32_t sb, const float* __restrict__ x, long row0, int n, int t) {
    int r = t >> 2, q = t & 3;
    long gr = row0 + r;
    bool v = gr < (long)n;
    const float4* src = (const float4*)(x + gr * 512 + 128 + q * 96);
    uint32_t rb = (uint32_t)r * 256u, s = (uint32_t)(r & 7);
    #pragma unroll
    for (int mm = 0; mm < 8; ++mm) {
        float a[12];
        #pragma unroll
        for (int j = 0; j < 3; ++j) {
            float4 xv = v ? src[mm * 3 + j] : make_float4(0.f, 0.f, 0.f, 0.f);
            a[j * 4 + 0] = xv.x; a[j * 4 + 1] = xv.y; a[j * 4 + 2] = xv.z; a[j * 4 + 3] = xv.w;
        }
        uint32_t u0 = (uint32_t)(q * 32 + mm * 4);
        uint32_t off = rb + (((u0 >> 3) ^ s) << 4) + ((u0 >> 2) & 1) * 8;
        #pragma unroll
        for (int i = 0; i < 3; ++i)
            sts64(sb + SLOT(i) + off, pack2(a[i], a[i + 3]), pack2(a[i + 6], a[i + 9]));
    }
}

// ======================= dual GEMM (64x128 out, K=128, 2 B matrices) ==========
// acc1 += (c1 .* A) @ B1,  acc2 += (c2 .* A) @ B2; A read once via ldmatrix.
DINLINE void dual64(uint32_t xslot, const uint4* __restrict__ pB1,
                    const uint4* __restrict__ pB2,
                    const uint32_t (&c1)[2][2], const uint32_t (&c2)[2][2],
                    float (&acc1)[2][4][4], float (&acc2)[2][4][4],
                    int wm, int lane) {
    const uint32_t rA = (uint32_t)(wm * 32 + (lane & 15));
    const uint32_t cA = (uint32_t)((lane >> 4) & 1);
    const uint32_t sA = rA & 7;
    const uint32_t bA0 = xslot + rA * 256u, bA1 = bA0 + 4096u;
    #pragma unroll
    for (int kc = 0; kc < 8; ++kc) {
        uint32_t a0[4], a1[4];
        uint32_t ka = (((((uint32_t)kc << 1) | cA) ^ sA) << 4);
        ldmx4(a0, bA0 + ka); ldmx4(a1, bA1 + ka);
        uint4 p = pB1[kc * 64], q = pB1[kc * 64 + 1];
        uint4 r = pB2[kc * 64], s = pB2[kc * 64 + 1];
        uint32_t t0[4], t1[4];
        // scaled for B1
        t0[0] = hmul2u(a0[0], c1[0][0]); t0[1] = hmul2u(a0[1], c1[0][1]);
        t0[2] = hmul2u(a0[2], c1[0][0]); t0[3] = hmul2u(a0[3], c1[0][1]);
        t1[0] = hmul2u(a1[0], c1[1][0]); t1[1] = hmul2u(a1[1], c1[1][1]);
        t1[2] = hmul2u(a1[2], c1[1][0]); t1[3] = hmul2u(a1[3], c1[1][1]);
        mmaf16(acc1[0][0], t0, p.x, p.y); mmaf16(acc1[0][1], t0, p.z, p.w);
        mmaf16(acc1[0][2], t0, q.x, q.y); mmaf16(acc1[0][3], t0, q.z, q.w);
        mmaf16(acc1[1][0], t1, p.x, p.y); mmaf16(acc1[1][1], t1, p.z, p.w);
        mmaf16(acc1[1][2], t1, q.x, q.y); mmaf16(acc1[1][3], t1, q.z, q.w);
        // scaled for B2
        t0[0] = hmul2u(a0[0], c2[0][0]); t0[1] = hmul2u(a0[1], c2[0][1]);
        t0[2] = hmul2u(a0[2], c2[0][0]); t0[3] = hmul2u(a0[3], c2[0][1]);
        t1[0] = hmul2u(a1[0], c2[1][0]); t1[1] = hmul2u(a1[1], c2[1][1]);
        t1[2] = hmul2u(a1[2], c2[1][0]); t1[3] = hmul2u(a1[3], c2[1][1]);
        mmaf16(acc2[0][0], t0, r.x, r.y); mmaf16(acc2[0][1], t0, r.z, r.w);
        mmaf16(acc2[0][2], t0, s.x, s.y); mmaf16(acc2[0][3], t0, s.z, s.w);
        mmaf16(acc2[1][0], t1, r.x, r.y); mmaf16(acc2[1][1], t1, r.z, r.w);
        mmaf16(acc2[1][2], t1, s.x, s.y); mmaf16(acc2[1][3], t1, s.z, s.w);
    }
}
DINLINE void zacc(float (&a)[2][4][4]) {
    #pragma unroll
    for (int m = 0; m < 2; ++m)
        #pragma unroll
        for (int g = 0; g < 4; ++g)
            #pragma unroll
            for (int e = 0; e < 4; ++e) a[m][g][e] = 0.0f;
}

// ======================= main kernel =======================
__global__ void __launch_bounds__(256, 2) o3tp_main(
    const float* __restrict__ x, const float* __restrict__ y,
    const float* __restrict__ bias, float* __restrict__ out, int n)
{
    extern __shared__ char smem[];
    const uint32_t sb = smem_u32(smem);
    const int t = threadIdx.x, lane = t & 31, wid = t >> 5;
    const int wm = wid & 1, wn = wid >> 1;
    const long row0 = (long)blockIdx.x * 64;

    fill_x0(sb + SLOT(0), x, row0, n, t);

    // per-thread c-frag rows & y values
    int rl[2]; long gr0[2]; bool va[2], vb[2];
    float yv[2][2][4];
    #pragma unroll
    for (int mf = 0; mf < 2; ++mf) {
        rl[mf] = wm * 32 + mf * 16 + (lane >> 2);
        gr0[mf] = row0 + rl[mf];
        va[mf] = gr0[mf] < (long)n;
        vb[mf] = gr0[mf] + 8 < (long)n;
        #pragma unroll
        for (int e = 0; e < 4; ++e) { yv[mf][0][e] = 0.f; yv[mf][1][e] = 0.f; }
        if (va[mf]) { float4 v = *(const float4*)(y + gr0[mf] * 4);
            yv[mf][0][0] = v.x; yv[mf][0][1] = v.y; yv[mf][0][2] = v.z; yv[mf][0][3] = v.w; }
        if (vb[mf]) { float4 v = *(const float4*)(y + (gr0[mf] + 8) * 4);
            yv[mf][1][0] = v.x; yv[mf][1][1] = v.y; yv[mf][1][2] = v.z; yv[mf][1][3] = v.w; }
    }

    // scale constants (half2 broadcast)
    uint32_t y0h[2][2], s3y0h[2][2], onesh[2][2];
    #pragma unroll
    for (int mf = 0; mf < 2; ++mf)
        #pragma unroll
        for (int h = 0; h < 2; ++h) {
            y0h[mf][h]   = h2u(__float2half2_rn(yv[mf][h][0]));
            s3y0h[mf][h] = h2u(__float2half2_rn(S3 * yv[mf][h][0]));
            onesh[mf][h] = h2u(__float2half2_rn(1.0f));
        }

    // warp B-fragment pointers: base + ((j*4+wn)*2048 + lane*8) u32
    const uint32_t wl = (uint32_t)(wn * 2048 + lane * 8);
    const uint4* pW000 = (const uint4*)(g_Wb + 0 * 8192 + wl);
    const uint4* pW011 = (const uint4*)(g_Wb + 1 * 8192 + wl);
    const uint4* pW110 = (const uint4*)(g_Wb + 2 * 8192 + wl);
    const uint4* pW101 = (const uint4*)(g_Wb + 3 * 8192 + wl);

    float o0[2][4][4], aux[2][4][4];
    zacc(o0); zacc(aux);
    __syncthreads();

    // ---- phase 1: o0 += (y0*X0)@W000 ; p011 = X0@W011 ----
    dual64(sb + SLOT(0), pW000, pW011, y0h, onesh, o0, aux, wm, lane);

    // compress p011 to 16 half2 regs
    uint32_t p011h[16];
    #pragma unroll
    for (int mf = 0; mf < 2; ++mf)
        #pragma unroll
        for (int g = 0; g < 4; ++g) {
            p011h[mf * 8 + g * 2 + 0] = pack2(aux[mf][g][0], aux[mf][g][1]);
            p011h[mf * 8 + g * 2 + 1] = pack2(aux[mf][g][2], aux[mf][g][3]);
        }

    __syncthreads();                 // all warps done reading X0
    fill_x1(sb, x, row0, n, t);      // X1_0/1/2 -> slots 0/1/2
    __syncthreads();

    // ---- phase 2: per i: o0 += (S3*y1_i*X1_i)@W110 ;
    //                      o1_i = S3*y1_i*p011 + (S3*y0*X1_i)@W101 -> plane_i ----
    #pragma unroll 1
    for (int i = 0; i < 3; ++i) {
        uint32_t c1[2][2];
        float s1[2][2];
        #pragma unroll
        for (int mf = 0; mf < 2; ++mf)
            #pragma unroll
            for (int h = 0; h < 2; ++h) {
                s1[mf][h] = S3 * yv[mf][h][1 + i];
                c1[mf][h] = h2u(__float2half2_rn(s1[mf][h]));
            }
        // seed aux = S3*y1_i * p011
        #pragma unroll
        for (int mf = 0; mf < 2; ++mf)
            #pragma unroll
            for (int g = 0; g < 4; ++g) {
                float2 plo = __half22float2(u2h(p011h[mf * 8 + g * 2 + 0]));
                float2 phi = __half22float2(u2h(p011h[mf * 8 + g * 2 + 1]));
                aux[mf][g][0] = s1[mf][0] * plo.x; aux[mf][g][1] = s1[mf][0] * plo.y;
                aux[mf][g][2] = s1[mf][1] * phi.x; aux[mf][g][3] = s1[mf][1] * phi.y;
            }
        dual64(sb + SLOT(i), pW110, pW101, c1, s3y0h, o0, aux, wm, lane);
        __syncthreads();  // all warps done reading slot i
        // stage o1_i as f16 plane (pitch 132 halves)
        #pragma unroll
        for (int mf = 0; mf < 2; ++mf)
            #pragma unroll
            for (int g = 0; g < 4; ++g) {
                uint32_t w0 = (uint32_t)(wn * 32 + g * 8 + 2 * (lane & 3));
                sts32(sb + SLOT(i) + ((uint32_t)rl[mf] * 132u + w0) * 2u,
                      pack2(aux[mf][g][0], aux[mf][g][1]));
                sts32(sb + SLOT(i) + ((uint32_t)(rl[mf] + 8) * 132u + w0) * 2u,
                      pack2(aux[mf][g][2], aux[mf][g][3]));
            }
    }

    // ---- store o0 + bias (coalesced float2) ----
    #pragma unroll
    for (int mf = 0; mf < 2; ++mf)
        #pragma unroll
        for (int g = 0; g < 4; ++g) {
            const int w0 = wn * 32 + g * 8 + 2 * (lane & 3);
            const float b0 = __ldg(bias + w0), b1 = __ldg(bias + w0 + 1);
            if (va[mf]) { float2 o = make_float2(o0[mf][g][0] + b0, o0[mf][g][1] + b1);
                          *(float2*)(out + gr0[mf] * 512 + w0) = o; }
            if (vb[mf]) { float2 o = make_float2(o0[mf][g][2] + b0, o0[mf][g][3] + b1);
                          *(float2*)(out + (gr0[mf] + 8) * 512 + w0) = o; }
        }
    __syncthreads();

    // ---- final: interleave planes -> out[:, 128:512], STG.128 ----
    {
        const int r = t >> 2, q = t & 3;
        const long gr = row0 + r;
        if (gr < (long)n) {
            float* dst = out + gr * 512 + 128 + q * 96;
            const uint32_t pb = (uint32_t)r * 264u;
            #pragma unroll
            for (int mm = 0; mm < 8; ++mm) {
                const uint32_t w0 = (uint32_t)(q * 32 + mm * 4);
                float p[3][4];
                #pragma unroll
                for (int i = 0; i < 3; ++i) {
                    uint32_t a = sb + SLOT(i) + pb + w0 * 2u;
                    float2 lo = __half22float2(u2h(lds32(a)));
                    float2 hi = __half22float2(u2h(lds32(a + 4u)));
                    p[i][0] = lo.x; p[i][1] = lo.y; p[i][2] = hi.x; p[i][3] = hi.y;
                }
                float4 f0 = make_float4(p[0][0], p[1][0], p[2][0], p[0][1]);
                float4 f1 = make_float4(p[1][1], p[2][1], p[0][2], p[1][2]);
                float4 f2 = make_float4(p[2][2], p[0][3], p[1][3], p[2][3]);
                *(float4*)(dst + mm * 12)     = f0;
                *(float4*)(dst + mm * 12 + 4) = f1;
                *(float4*)(dst + mm * 12 + 8) = f2;
            }
        }
    }
}

// ======================= launch =======================
extern "C" void kernel_launch(void* const* d_in, const int* in_sizes, int n_in,
                              void* d_out, int out_size) {
    const float* x    = (const float*)d_in[0];
    const float* y    = (const float*)d_in[1];
    const float* W000 = (const float*)d_in[2];
    const float* W011 = (const float*)d_in[3];
    const float* W101 = (const float*)d_in[4];
    const float* W110 = (const float*)d_in[5];
    const float* bias = (const float*)d_in[6];

    int n = in_sizes[1] / 4;  // y is (n, 4)
    if (n <= 0) return;

    o3tp_prep<<<128, 256>>>(W000, W011, W110, W101);

    cudaFuncSetAttribute(o3tp_main, cudaFuncAttributeMaxDynamicSharedMemorySize, SMEM_TOTAL);
    int grid = (n + 63) / 64;
    o3tp_main<<<grid, 256, SMEM_TOTAL>>>(x, y, bias, (float*)d_out, n);
}

// round 7
// speedup vs baseline: 4.6133x; 1.5643x over previous
#include <cuda_runtime.h>
#include <cuda_fp16.h>
#include <cstdint>

#define DINLINE __device__ __forceinline__
static __device__ constexpr float S3 = 0.57735026918962576451f;  // 1/sqrt(3)

// ======================= low-level helpers =======================
DINLINE uint32_t smem_u32(const void* p) {
    uint32_t a;
    asm("{ .reg .u64 t; cvta.to.shared.u64 t, %1; cvt.u32.u64 %0, t; }" : "=r"(a) : "l"(p));
    return a;
}
DINLINE void sts64(uint32_t a, uint32_t lo, uint32_t hi) {
    asm volatile("st.shared.v2.b32 [%0], {%1,%2};" :: "r"(a), "r"(lo), "r"(hi));
}
DINLINE void sts32(uint32_t a, uint32_t v) {
    asm volatile("st.shared.b32 [%0], %1;" :: "r"(a), "r"(v));
}
DINLINE void sts16(uint32_t a, unsigned short v) {
    asm volatile("st.shared.b16 [%0], %1;" :: "r"(a), "h"(v));
}
DINLINE unsigned short lds16(uint32_t a) {
    unsigned short v;
    asm volatile("ld.shared.b16 %0, [%1];" : "=h"(v) : "r"(a));
    return v;
}
DINLINE void ldmx4(uint32_t (&v)[4], uint32_t a) {
    asm volatile("ldmatrix.sync.aligned.m8n8.x4.shared.b16 {%0,%1,%2,%3}, [%4];"
                 : "=r"(v[0]), "=r"(v[1]), "=r"(v[2]), "=r"(v[3]) : "r"(a));
}
DINLINE void mmaf16(float (&d)[4], const uint32_t (&a)[4], uint32_t b0, uint32_t b1) {
    asm volatile(
        "mma.sync.aligned.m16n8k16.row.col.f32.f16.f16.f32 "
        "{%0,%1,%2,%3}, {%4,%5,%6,%7}, {%8,%9}, {%0,%1,%2,%3};"
        : "+f"(d[0]), "+f"(d[1]), "+f"(d[2]), "+f"(d[3])
        : "r"(a[0]), "r"(a[1]), "r"(a[2]), "r"(a[3]), "r"(b0), "r"(b1));
}
DINLINE uint32_t h2u(__half2 h) { return *reinterpret_cast<uint32_t*>(&h); }
DINLINE __half2  u2h(uint32_t u) { return *reinterpret_cast<__half2*>(&u); }
DINLINE uint32_t pack2(float a, float b) { return h2u(__floats2half2_rn(a, b)); }
DINLINE uint32_t hmul2u(uint32_t a, uint32_t b) { return h2u(__hmul2(u2h(a), u2h(b))); }
DINLINE unsigned short h2us(__half h) { return *reinterpret_cast<unsigned short*>(&h); }
DINLINE float us2f(unsigned short u) { __half h = *reinterpret_cast<__half*>(&u); return __half2float(h); }

// ======================= geometry =======================
// CTA 256 thr = 8 warps; tile 64 rows x 128 w-cols; warp tile 32x32 (grid 2m x 4n).
// X rows in smem: 128 f16 = 256 B = 16 chunks of 16 B, XOR swizzle chunk' = c ^ (row&7).
static constexpr uint32_t SLOT_B = 16896;   // raw X 16384 B; as plane 64 x 132h x 2B
#define SLOT(i) ((uint32_t)(i) * SLOT_B)
static constexpr uint32_t SMEM_TOTAL = 3 * SLOT_B;  // 50688

// Fragment-ordered global weights for direct lane-contiguous LDG.128:
// u32 index = ((j*4+wn)*8+kc)*256 + h*128 + lane*4 + e   (e in 0..3)
//   n = wn*32 + h*16 + ((e>>1)&1)*8 + (lane>>2)
//   k = kc*16 + (e&1)*8 + 2*(lane&3); value = half2(W[k][n], W[k+1][n])
// j: 0=W000, 1=W011, 2=W110, 3=W101 (source [k][n] = src[k*128+n])
__device__ __align__(16) uint32_t g_Wb[4 * 8192];

__global__ void o3tp_prep(const float* __restrict__ W000, const float* __restrict__ W011,
                          const float* __restrict__ W110, const float* __restrict__ W101) {
    int idx = blockIdx.x * blockDim.x + threadIdx.x;  // 0..32767
    int e = idx & 3, lane = (idx >> 2) & 31, h = (idx >> 7) & 1;
    int kc = (idx >> 8) & 7, wn = (idx >> 11) & 3, j = idx >> 13;
    int n = wn * 32 + h * 16 + ((e >> 1) & 1) * 8 + (lane >> 2);
    int k = kc * 16 + (e & 1) * 8 + 2 * (lane & 3);
    const float* src = (j == 0) ? W000 : (j == 1) ? W011 : (j == 2) ? W110 : W101;
    g_Wb[idx] = pack2(src[k * 128 + n], src[(k + 1) * 128 + n]);
}

// ======================= X fills (warp-per-row, lane-contiguous LDG) ==========
DINLINE void fill_x0(uint32_t slot, const float* __restrict__ x, long row0, int n,
                     int wid, int lane) {
    #pragma unroll
    for (int it = 0; it < 8; ++it) {
        int r = it * 8 + wid;
        long gr = row0 + r;
        float4 xv = (gr < (long)n) ? ((const float4*)(x + gr * 512))[lane]
                                   : make_float4(0.f, 0.f, 0.f, 0.f);
        // k = lane*4 -> chunk = lane>>1, half-of-chunk = lane&1
        uint32_t a = slot + (uint32_t)r * 256u
                   + ((((uint32_t)lane >> 1) ^ (uint32_t)(r & 7)) << 4)
                   + (uint32_t)(lane & 1) * 8u;
        sts64(a, pack2(xv.x, xv.y), pack2(xv.z, xv.w));
    }
}
// X1: read x[:,128:512] lane-contiguous; scatter halves into 3 swizzled slots
DINLINE void fill_x1(uint32_t sb, const float* __restrict__ x, long row0, int n,
                     int wid, int lane) {
    #pragma unroll
    for (int it = 0; it < 8; ++it) {
        int r = it * 8 + wid;
        long gr = row0 + r;
        bool v = gr < (long)n;
        const float4* src = (const float4*)(x + gr * 512 + 128);
        uint32_t rowb = (uint32_t)r * 256u, s = (uint32_t)(r & 7);
        #pragma unroll
        for (int m = 0; m < 3; ++m) {
            float4 xv = v ? src[m * 32 + lane] : make_float4(0.f, 0.f, 0.f, 0.f);
            float el[4] = {xv.x, xv.y, xv.z, xv.w};
            #pragma unroll
            for (int j = 0; j < 4; ++j) {
                uint32_t e = (uint32_t)(m * 128 + lane * 4 + j);
                uint32_t u = (e * 21846u) >> 16;     // e/3
                uint32_t i = e - 3u * u;             // e%3
                uint32_t a = sb + i * SLOT_B + rowb
                           + ((((u >> 3) & 15u) ^ s) << 4) + (u & 7u) * 2u;
                sts16(a, h2us(__float2half_rn(el[j])));
            }
        }
    }
}

// ======================= dual GEMM (64x128 out, K=128, 2 B matrices) ==========
// acc1 += (c1 .* A) @ B1,  acc2 += (c2 .* A) @ B2; A read once via ldmatrix.
DINLINE void dual64(uint32_t xslot, const uint4* __restrict__ pB1,
                    const uint4* __restrict__ pB2,
                    const uint32_t (&c1)[2][2], const uint32_t (&c2)[2][2],
                    float (&acc1)[2][4][4], float (&acc2)[2][4][4],
                    int wm, int lane) {
    const uint32_t rA = (uint32_t)(wm * 32 + (lane & 15));
    const uint32_t cA = (uint32_t)((lane >> 4) & 1);
    const uint32_t sA = rA & 7;
    const uint32_t bA0 = xslot + rA * 256u, bA1 = bA0 + 4096u;
    #pragma unroll
    for (int kc = 0; kc < 8; ++kc) {
        uint32_t a0[4], a1[4];
        uint32_t ka = (((((uint32_t)kc << 1) | cA) ^ sA) << 4);
        ldmx4(a0, bA0 + ka); ldmx4(a1, bA1 + ka);
        uint4 p = pB1[kc * 64], q = pB1[kc * 64 + 32];
        uint4 r = pB2[kc * 64], s = pB2[kc * 64 + 32];
        uint32_t t0[4], t1[4];
        // scaled for B1
        t0[0] = hmul2u(a0[0], c1[0][0]); t0[1] = hmul2u(a0[1], c1[0][1]);
        t0[2] = hmul2u(a0[2], c1[0][0]); t0[3] = hmul2u(a0[3], c1[0][1]);
        t1[0] = hmul2u(a1[0], c1[1][0]); t1[1] = hmul2u(a1[1], c1[1][1]);
        t1[2] = hmul2u(a1[2], c1[1][0]); t1[3] = hmul2u(a1[3], c1[1][1]);
        mmaf16(acc1[0][0], t0, p.x, p.y); mmaf16(acc1[0][1], t0, p.z, p.w);
        mmaf16(acc1[0][2], t0, q.x, q.y); mmaf16(acc1[0][3], t0, q.z, q.w);
        mmaf16(acc1[1][0], t1, p.x, p.y); mmaf16(acc1[1][1], t1, p.z, p.w);
        mmaf16(acc1[1][2], t1, q.x, q.y); mmaf16(acc1[1][3], t1, q.z, q.w);
        // scaled for B2
        t0[0] = hmul2u(a0[0], c2[0][0]); t0[1] = hmul2u(a0[1], c2[0][1]);
        t0[2] = hmul2u(a0[2], c2[0][0]); t0[3] = hmul2u(a0[3], c2[0][1]);
        t1[0] = hmul2u(a1[0], c2[1][0]); t1[1] = hmul2u(a1[1], c2[1][1]);
        t1[2] = hmul2u(a1[2], c2[1][0]); t1[3] = hmul2u(a1[3], c2[1][1]);
        mmaf16(acc2[0][0], t0, r.x, r.y); mmaf16(acc2[0][1], t0, r.z, r.w);
        mmaf16(acc2[0][2], t0, s.x, s.y); mmaf16(acc2[0][3], t0, s.z, s.w);
        mmaf16(acc2[1][0], t1, r.x, r.y); mmaf16(acc2[1][1], t1, r.z, r.w);
        mmaf16(acc2[1][2], t1, s.x, s.y); mmaf16(acc2[1][3], t1, s.z, s.w);
    }
}
DINLINE void zacc(float (&a)[2][4][4]) {
    #pragma unroll
    for (int m = 0; m < 2; ++m)
        #pragma unroll
        for (int g = 0; g < 4; ++g)
            #pragma unroll
            for (int e = 0; e < 4; ++e) a[m][g][e] = 0.0f;
}

// ======================= main kernel =======================
__global__ void __launch_bounds__(256, 2) o3tp_main(
    const float* __restrict__ x, const float* __restrict__ y,
    const float* __restrict__ bias, float* __restrict__ out, int n)
{
    extern __shared__ char smem[];
    const uint32_t sb = smem_u32(smem);
    const int t = threadIdx.x, lane = t & 31, wid = t >> 5;
    const int wm = wid & 1, wn = wid >> 1;
    const long row0 = (long)blockIdx.x * 64;

    fill_x0(sb + SLOT(0), x, row0, n, wid, lane);

    // per-thread c-frag rows & y values
    int rl[2]; long gr0[2]; bool va[2], vb[2];
    float yv[2][2][4];
    #pragma unroll
    for (int mf = 0; mf < 2; ++mf) {
        rl[mf] = wm * 32 + mf * 16 + (lane >> 2);
        gr0[mf] = row0 + rl[mf];
        va[mf] = gr0[mf] < (long)n;
        vb[mf] = gr0[mf] + 8 < (long)n;
        #pragma unroll
        for (int e = 0; e < 4; ++e) { yv[mf][0][e] = 0.f; yv[mf][1][e] = 0.f; }
        if (va[mf]) { float4 v = *(const float4*)(y + gr0[mf] * 4);
            yv[mf][0][0] = v.x; yv[mf][0][1] = v.y; yv[mf][0][2] = v.z; yv[mf][0][3] = v.w; }
        if (vb[mf]) { float4 v = *(const float4*)(y + (gr0[mf] + 8) * 4);
            yv[mf][1][0] = v.x; yv[mf][1][1] = v.y; yv[mf][1][2] = v.z; yv[mf][1][3] = v.w; }
    }

    // scale constants (half2 broadcast)
    uint32_t y0h[2][2], s3y0h[2][2], onesh[2][2];
    #pragma unroll
    for (int mf = 0; mf < 2; ++mf)
        #pragma unroll
        for (int h = 0; h < 2; ++h) {
            y0h[mf][h]   = h2u(__float2half2_rn(yv[mf][h][0]));
            s3y0h[mf][h] = h2u(__float2half2_rn(S3 * yv[mf][h][0]));
            onesh[mf][h] = h2u(__float2half2_rn(1.0f));
        }

    // warp B-fragment pointers (uint4 units): matrix j at j*2048, wn at wn*512
    const uint4* wbase = (const uint4*)g_Wb;
    const uint4* pW000 = wbase + 0 * 2048 + wn * 512 + lane;
    const uint4* pW011 = wbase + 1 * 2048 + wn * 512 + lane;
    const uint4* pW110 = wbase + 2 * 2048 + wn * 512 + lane;
    const uint4* pW101 = wbase + 3 * 2048 + wn * 512 + lane;

    float o0[2][4][4], aux[2][4][4];
    zacc(o0); zacc(aux);
    __syncthreads();

    // ---- phase 1: o0 += (y0*X0)@W000 ; p011 = X0@W011 ----
    dual64(sb + SLOT(0), pW000, pW011, y0h, onesh, o0, aux, wm, lane);

    // compress p011 to 16 half2 regs
    uint32_t p011h[16];
    #pragma unroll
    for (int mf = 0; mf < 2; ++mf)
        #pragma unroll
        for (int g = 0; g < 4; ++g) {
            p011h[mf * 8 + g * 2 + 0] = pack2(aux[mf][g][0], aux[mf][g][1]);
            p011h[mf * 8 + g * 2 + 1] = pack2(aux[mf][g][2], aux[mf][g][3]);
        }

    __syncthreads();                        // all warps done reading X0
    fill_x1(sb, x, row0, n, wid, lane);     // X1_0/1/2 -> slots 0/1/2
    __syncthreads();

    // ---- phase 2: per i: o0 += (S3*y1_i*X1_i)@W110 ;
    //                      o1_i = S3*y1_i*p011 + (S3*y0*X1_i)@W101 -> plane_i ----
    #pragma unroll 1
    for (int i = 0; i < 3; ++i) {
        uint32_t c1[2][2];
        float s1[2][2];
        #pragma unroll
        for (int mf = 0; mf < 2; ++mf)
            #pragma unroll
            for (int h = 0; h < 2; ++h) {
                s1[mf][h] = S3 * yv[mf][h][1 + i];
                c1[mf][h] = h2u(__float2half2_rn(s1[mf][h]));
            }
        // seed aux = S3*y1_i * p011
        #pragma unroll
        for (int mf = 0; mf < 2; ++mf)
            #pragma unroll
            for (int g = 0; g < 4; ++g) {
                float2 plo = __half22float2(u2h(p011h[mf * 8 + g * 2 + 0]));
                float2 phi = __half22float2(u2h(p011h[mf * 8 + g * 2 + 1]));
                aux[mf][g][0] = s1[mf][0] * plo.x; aux[mf][g][1] = s1[mf][0] * plo.y;
                aux[mf][g][2] = s1[mf][1] * phi.x; aux[mf][g][3] = s1[mf][1] * phi.y;
            }
        dual64(sb + SLOT(i), pW110, pW101, c1, s3y0h, o0, aux, wm, lane);
        __syncthreads();  // all warps done reading slot i
        // stage o1_i as f16 plane (pitch 132 halves)
        #pragma unroll
        for (int mf = 0; mf < 2; ++mf)
            #pragma unroll
            for (int g = 0; g < 4; ++g) {
                uint32_t w0 = (uint32_t)(wn * 32 + g * 8 + 2 * (lane & 3));
                sts32(sb + SLOT(i) + ((uint32_t)rl[mf] * 132u + w0) * 2u,
                      pack2(aux[mf][g][0], aux[mf][g][1]));
                sts32(sb + SLOT(i) + ((uint32_t)(rl[mf] + 8) * 132u + w0) * 2u,
                      pack2(aux[mf][g][2], aux[mf][g][3]));
            }
    }

    // ---- store o0 + bias (float2, frag-direct) ----
    #pragma unroll
    for (int mf = 0; mf < 2; ++mf)
        #pragma unroll
        for (int g = 0; g < 4; ++g) {
            const int w0 = wn * 32 + g * 8 + 2 * (lane & 3);
            const float b0 = __ldg(bias + w0), b1 = __ldg(bias + w0 + 1);
            if (va[mf]) { float2 o = make_float2(o0[mf][g][0] + b0, o0[mf][g][1] + b1);
                          *(float2*)(out + gr0[mf] * 512 + w0) = o; }
            if (vb[mf]) { float2 o = make_float2(o0[mf][g][2] + b0, o0[mf][g][3] + b1);
                          *(float2*)(out + (gr0[mf] + 8) * 512 + w0) = o; }
        }
    __syncthreads();

    // ---- final: interleave planes -> out[:, 128:512], warp-per-row STG.128 ----
    #pragma unroll 1
    for (int it = 0; it < 8; ++it) {
        int r = it * 8 + wid;
        long gr = row0 + r;
        if (gr < (long)n) {
            float4* dst = (float4*)(out + gr * 512 + 128);
            uint32_t pb = sb + (uint32_t)r * 264u;
            #pragma unroll
            for (int m = 0; m < 3; ++m) {
                uint32_t e0 = (uint32_t)(m * 128 + lane * 4);
                float o[4];
                #pragma unroll
                for (int j = 0; j < 4; ++j) {
                    uint32_t e = e0 + j;
                    uint32_t u = (e * 21846u) >> 16;   // e/3
                    uint32_t i = e - 3u * u;           // e%3
                    o[j] = us2f(lds16(pb + i * SLOT_B + u * 2u));
                }
                dst[m * 32 + lane] = make_float4(o[0], o[1], o[2], o[3]);
            }
        }
    }
}

// ======================= launch =======================
extern "C" void kernel_launch(void* const* d_in, const int* in_sizes, int n_in,
                              void* d_out, int out_size) {
    const float* x    = (const float*)d_in[0];
    const float* y    = (const float*)d_in[1];
    const float* W000 = (const float*)d_in[2];
    const float* W011 = (const float*)d_in[3];
    const float* W101 = (const float*)d_in[4];
    const float* W110 = (const float*)d_in[5];
    const float* bias = (const float*)d_in[6];

    int n = in_sizes[1] / 4;  // y is (n, 4)
    if (n <= 0) return;

    o3tp_prep<<<128, 256>>>(W000, W011, W110, W101);

    cudaFuncSetAttribute(o3tp_main, cudaFuncAttributeMaxDynamicSharedMemorySize, SMEM_TOTAL);
    int grid = (n + 63) / 64;
    o3tp_main<<<grid, 256, SMEM_TOTAL>>>(x, y, bias, (float*)d_out, n);
}